// round 10
// baseline (speedup 1.0000x reference)
#include <cuda_runtime.h>
#include <math.h>
#include <stdint.h>

#define HIDDEN 2048
#define SEQ    1024
#define BATCH  2
#define NHEADS 32
#define NGROUP 8
#define HDIM   64
#define MTOT   (BATCH * SEQ)
#define KVW    (NGROUP * HDIM)    /* 512  */
#define QKVW   (HIDDEN + 2 * KVW) /* 3072 */

/* ---------------- scratch (no cudaMalloc allowed) ---------------- */
__device__ float g_xt [MTOT * HIDDEN];               /* tf32 x; later oproj partial */
__device__ float g_wt [QKVW * HIDDEN];               /* Wq|Wk|Wv tf32  */
__device__ float g_wot[HIDDEN * HIDDEN];             /* Wo tf32        */
__device__ float g_q  [MTOT * HIDDEN];               /* fp32           */
__device__ float g_k  [MTOT * KVW];                  /* tf32 bits      */
__device__ float g_vt [BATCH * NGROUP * HDIM * SEQ]; /* tf32, [b,g,d,s]*/
__device__ float g_attn[MTOT * HIDDEN];              /* tf32 bits      */
__device__ int   g_flags[256];                       /* split-K flags  */

/* ---------------- helpers ---------------- */
__device__ __forceinline__ uint32_t f2tf32(float x) {
    uint32_t r;
    asm("cvt.rna.tf32.f32 %0, %1;" : "=r"(r) : "f"(x));
    return r;
}
__device__ __forceinline__ uint32_t smem_u32(const void* p) {
    uint32_t a;
    asm("{ .reg .u64 t; cvta.to.shared.u64 t, %1; cvt.u32.u64 %0, t; }"
        : "=r"(a) : "l"(p));
    return a;
}
__device__ __forceinline__ void mma_tf32(float* c, const uint32_t* a,
                                         uint32_t b0, uint32_t b1) {
    asm volatile(
        "mma.sync.aligned.m16n8k8.row.col.f32.tf32.tf32.f32 "
        "{%0,%1,%2,%3}, {%4,%5,%6,%7}, {%8,%9}, {%0,%1,%2,%3};"
        : "+f"(c[0]), "+f"(c[1]), "+f"(c[2]), "+f"(c[3])
        : "r"(a[0]), "r"(a[1]), "r"(a[2]), "r"(a[3]), "r"(b0), "r"(b1));
}
__device__ __forceinline__ void ldsm_x4(uint32_t* r, uint32_t addr) {
    asm volatile("ldmatrix.sync.aligned.m8n8.x4.shared.b16 {%0,%1,%2,%3}, [%4];"
        : "=r"(r[0]), "=r"(r[1]), "=r"(r[2]), "=r"(r[3]) : "r"(addr));
}
__device__ __forceinline__ void cp16(uint32_t dst, const void* src) {
    asm volatile("cp.async.cg.shared.global [%0], [%1], 16;"
                 :: "r"(dst), "l"(src));
}
#define CP_COMMIT() asm volatile("cp.async.commit_group;" ::: "memory")
#define CP_WAIT0()  asm volatile("cp.async.wait_group 0;"  ::: "memory")
#define CP_WAIT1()  asm volatile("cp.async.wait_group 1;"  ::: "memory")

/* =================================================================
 * Pre-convert x, Wq|Wk|Wv, Wo to tf32 bits (grid-stride, float4).
 * ================================================================= */
__global__ void cvt_all(const float4* __restrict__ x,
                        const float4* __restrict__ wq,
                        const float4* __restrict__ wk,
                        const float4* __restrict__ wv,
                        const float4* __restrict__ wo)
{
    const int64_t N0 = 1048576;
    const int64_t N1 = N0 + 1048576;
    const int64_t N2 = N1 + 262144;
    const int64_t N3 = N2 + 262144;
    const int64_t N4 = N3 + 1048576;
    uint4* xt  = (uint4*)g_xt;
    uint4* wt  = (uint4*)g_wt;
    uint4* wot = (uint4*)g_wot;
    for (int64_t i = (int64_t)blockIdx.x * blockDim.x + threadIdx.x;
         i < N4; i += (int64_t)gridDim.x * blockDim.x) {
        float4 v; uint4* dst;
        if (i < N0)      { v = x [i];      dst = xt  + i; }
        else if (i < N1) { v = wq[i - N0]; dst = wt  + (i - N0); }
        else if (i < N2) { v = wk[i - N1]; dst = wt  + 1048576 + (i - N1); }
        else if (i < N3) { v = wv[i - N2]; dst = wt  + 1310720 + (i - N2); }
        else             { v = wo[i - N3]; dst = wot + (i - N3); }
        uint4 u;
        u.x = f2tf32(v.x); u.y = f2tf32(v.y);
        u.z = f2tf32(v.z); u.w = f2tf32(v.w);
        *dst = u;
    }
}

/* =================================================================
 * TF32 NT GEMM core, cp.async double-buffered, BK=32, XOR-swizzled
 * 128B rows. CTA 128x128, 4 warps (2x2), warp tile 64x64.
 * MODE: 0 fp32+bias | 1 tf32+bias | 2 tf32+bias transposed to g_vt |
 *       3 raw partial store to g_xt + release flag |
 *       4 acquire-spin, add partial from g_xt + bias, store.
 * ================================================================= */
#define BK    32
#define TILEB 16384
#define STAGE (2 * TILEB)
#define GEMM_SMEM (2 * STAGE)          /* 65536 */

template<int MODE>
__device__ __forceinline__ void gemm_core(
    const float* __restrict__ A, const float* __restrict__ Bm,
    const float* __restrict__ bias, float* __restrict__ C,
    int ldc, int lda, int Kl, int m0, int n0B, int n0C, int kOff)
{
    extern __shared__ char smem[];
    const uint32_t sb = smem_u32(smem);
    const int tid = threadIdx.x, lane = tid & 31, wid = tid >> 5;
    const int wm = (wid & 1) * 64, wn = (wid >> 1) * 64;
    const int grp = lane >> 3;

    const uint32_t xm   = (uint32_t)(lane & 7) << 4;
    const uint32_t rowA = (uint32_t)(wm + (lane & 7) + ((grp & 1) << 3)) * 128;
    const uint32_t rowB = (uint32_t)(wn + (lane & 7) + ((grp >> 1) << 3)) * 128;
    const uint32_t cA   = (uint32_t)(grp >> 1) << 4;
    const uint32_t cB   = (uint32_t)(grp & 1) << 4;

    float acc[4][8][4];
#pragma unroll
    for (int mt = 0; mt < 4; mt++)
#pragma unroll
        for (int nt = 0; nt < 8; nt++) {
            acc[mt][nt][0] = 0.f; acc[mt][nt][1] = 0.f;
            acc[mt][nt][2] = 0.f; acc[mt][nt][3] = 0.f;
        }

    const float* Ag = A  + (size_t)(m0  + tid) * lda + kOff;
    const float* Bg = Bm + (size_t)(n0B + tid) * lda + kOff;
    const uint32_t sRow = (uint32_t)tid * 128;
    const uint32_t sX   = (uint32_t)(tid & 7) << 4;
    const int nIter = Kl / BK;

#pragma unroll
    for (int i = 0; i < 8; i++) {
        const uint32_t d = sRow + (((uint32_t)i << 4) ^ sX);
        cp16(sb + d,         Ag + i * 4);
        cp16(sb + TILEB + d, Bg + i * 4);
    }
    CP_COMMIT();

    for (int it = 0; it < nIter; it++) {
        CP_WAIT0();
        __syncthreads();

        const uint32_t aB = sb + (it & 1) * STAGE;
        const uint32_t bB = aB + TILEB;
        const uint32_t nx = sb + ((it + 1) & 1) * STAGE;
        const bool pf = (it + 1 < nIter);
        const float* Ap = Ag + (it + 1) * BK;
        const float* Bp = Bg + (it + 1) * BK;

#pragma unroll
        for (int ks = 0; ks < 4; ks++) {
            if (pf) {
                const uint32_t d0 = sRow + ((((uint32_t)(2 * ks) << 4))     ^ sX);
                const uint32_t d1 = sRow + ((((uint32_t)(2 * ks + 1) << 4)) ^ sX);
                cp16(nx + d0,         Ap + (2 * ks) * 4);
                cp16(nx + d1,         Ap + (2 * ks + 1) * 4);
                cp16(nx + TILEB + d0, Bp + (2 * ks) * 4);
                cp16(nx + TILEB + d1, Bp + (2 * ks + 1) * 4);
            }
            const uint32_t ck = ((uint32_t)ks << 5);
            uint32_t af[4][4];
#pragma unroll
            for (int mt = 0; mt < 4; mt++)
                ldsm_x4(af[mt], aB + rowA + mt * 2048 + ((ck + cA) ^ xm));
            uint32_t bf[2][4];
            ldsm_x4(bf[0], bB + rowB + ((ck + cB) ^ xm));
#pragma unroll
            for (int nt2 = 0; nt2 < 4; nt2++) {
                const int c = nt2 & 1, n = 1 - c;
                if (nt2 < 3)
                    ldsm_x4(bf[n], bB + rowB + (nt2 + 1) * 2048 + ((ck + cB) ^ xm));
#pragma unroll
                for (int mt = 0; mt < 4; mt++) {
                    mma_tf32(acc[mt][2 * nt2],     af[mt], bf[c][0], bf[c][1]);
                    mma_tf32(acc[mt][2 * nt2 + 1], af[mt], bf[c][2], bf[c][3]);
                }
            }
        }
        CP_COMMIT();
    }

    const int r0 = lane >> 2, a4 = lane & 3;

    if (MODE == 4) {
        /* acquire partial-ready flag before reading g_xt */
        if (tid == 0) {
            int* fp = &g_flags[blockIdx.y * gridDim.x + blockIdx.x];
            int v;
            do {
                asm volatile("ld.global.acquire.gpu.b32 %0, [%1];"
                             : "=r"(v) : "l"(fp) : "memory");
                if (!v) __nanosleep(128);
            } while (!v);
            *fp = 0;   /* reset for next graph replay */
        }
        __syncthreads();
    }

#pragma unroll
    for (int mt = 0; mt < 4; mt++) {
#pragma unroll
        for (int nt = 0; nt < 8; nt++) {
            const int col = n0C + wn + nt * 8 + 2 * a4;
            const int rA = m0 + wm + mt * 16 + r0;
            if (MODE == 0 || MODE == 1 || MODE == 4) {
                const float b0 = bias[col], b1 = bias[col + 1];
                if (MODE == 0) {
                    *(float2*)&C[(size_t)rA * ldc + col] =
                        make_float2(acc[mt][nt][0] + b0, acc[mt][nt][1] + b1);
                    *(float2*)&C[(size_t)(rA + 8) * ldc + col] =
                        make_float2(acc[mt][nt][2] + b0, acc[mt][nt][3] + b1);
                } else if (MODE == 1) {
                    *(float2*)&C[(size_t)rA * ldc + col] = make_float2(
                        __uint_as_float(f2tf32(acc[mt][nt][0] + b0)),
                        __uint_as_float(f2tf32(acc[mt][nt][1] + b1)));
                    *(float2*)&C[(size_t)(rA + 8) * ldc + col] = make_float2(
                        __uint_as_float(f2tf32(acc[mt][nt][2] + b0)),
                        __uint_as_float(f2tf32(acc[mt][nt][3] + b1)));
                } else {
                    /* MODE 4: add z0 partial + bias */
                    float2 p0 = *(float2*)&g_xt[(size_t)rA * HIDDEN + col];
                    float2 p1 = *(float2*)&g_xt[(size_t)(rA + 8) * HIDDEN + col];
                    *(float2*)&C[(size_t)rA * ldc + col] =
                        make_float2(p0.x + acc[mt][nt][0] + b0,
                                    p0.y + acc[mt][nt][1] + b1);
                    *(float2*)&C[(size_t)(rA + 8) * ldc + col] =
                        make_float2(p1.x + acc[mt][nt][2] + b0,
                                    p1.y + acc[mt][nt][3] + b1);
                }
            } else if (MODE == 3) {
                *(float2*)&g_xt[(size_t)rA * HIDDEN + col] =
                    make_float2(acc[mt][nt][0], acc[mt][nt][1]);
                *(float2*)&g_xt[(size_t)(rA + 8) * HIDDEN + col] =
                    make_float2(acc[mt][nt][2], acc[mt][nt][3]);
            } else {
                /* MODE 2: transposed tf32 store into g_vt[b,g,d,s] */
                const float b0 = bias[col], b1 = bias[col + 1];
                const int r1 = rA + 8;
#pragma unroll
                for (int q = 0; q < 2; q++) {
                    const int r = q ? r1 : rA;
                    const size_t base =
                        ((size_t)((r >> 10) * 8 + (col >> 6)) * 64) * 1024
                        + (size_t)(r & 1023);
                    g_vt[base + (size_t)(col & 63) * 1024] =
                        __uint_as_float(f2tf32(acc[mt][nt][2 * q] + b0));
                    g_vt[base + (size_t)((col & 63) + 1) * 1024] =
                        __uint_as_float(f2tf32(acc[mt][nt][2 * q + 1] + b1));
                }
            }
        }
    }

    if (MODE == 3) {
        __threadfence();
        __syncthreads();
        if (tid == 0) {
            int* fp = &g_flags[blockIdx.y * gridDim.x + blockIdx.x];
            asm volatile("st.global.release.gpu.b32 [%0], %1;"
                         :: "l"(fp), "r"(1) : "memory");
        }
    }
}

/* fused QKV projection: grid (24, 16) */
__global__ __launch_bounds__(128, 3) void qkv_gemm(
    const float* __restrict__ bq, const float* __restrict__ bk,
    const float* __restrict__ bv)
{
    const int n0 = blockIdx.x * 128, m0 = blockIdx.y * 128;
    if (n0 < 2048)
        gemm_core<0>(g_xt, g_wt, bq, g_q, HIDDEN, HIDDEN, HIDDEN, m0, n0, n0, 0);
    else if (n0 < 2560)
        gemm_core<1>(g_xt, g_wt, bk, g_k, KVW, HIDDEN, HIDDEN, m0, n0, n0 - 2048, 0);
    else
        gemm_core<2>(g_xt, g_wt, bv, (float*)0, KVW, HIDDEN, HIDDEN, m0, n0, n0 - 2560, 0);
}

/* O projection, spin split-K=2: grid (16, 16, 2) */
__global__ __launch_bounds__(128, 3) void oproj_sk(
    const float* __restrict__ bo, float* __restrict__ out)
{
    const int m0 = blockIdx.y * 128, n0 = blockIdx.x * 128;
    if (blockIdx.z == 0)
        gemm_core<3>(g_attn, g_wot, bo, (float*)0, HIDDEN, HIDDEN,
                     HIDDEN / 2, m0, n0, n0, 0);
    else
        gemm_core<4>(g_attn, g_wot, bo, out, HIDDEN, HIDDEN,
                     HIDDEN / 2, m0, n0, n0, HIDDEN / 2);
}

/* =================================================================
 * Flash attention (causal, GQA): 128 q-rows/CTA, 256 thr, 8 warps.
 * K/V staged via cp.async (V pre-transposed tf32); P in registers
 * via lane-shuffle C-frag -> A-frag conversion. 1 barrier per tile.
 * ================================================================= */
#define KSTG  16384                    /* 64 rows x 256 B */
#define ASTG  (2 * KSTG)
#define ATT_SMEM (3 * ASTG)            /* 98304 */

__global__ __launch_bounds__(256, 2) void attn_tc(
    const float* __restrict__ Q, const float* __restrict__ Kp,
    const float* __restrict__ Vtg, float* __restrict__ Out)
{
    extern __shared__ char smA[];
    const uint32_t sb = smem_u32(smA);

    const int qt = (int)gridDim.x - 1 - (int)blockIdx.x;  /* longest first */
    const int h = blockIdx.y, b = blockIdx.z, g = h >> 2;
    const int tid = threadIdx.x, lane = tid & 31, w = tid >> 5;
    const int r0 = lane >> 2, a4 = lane & 3;
    const int grp = lane >> 3;

    const int srow = tid >> 2, csel = tid & 3;
    const float* ksrc = Kp  + ((size_t)(b * SEQ) + srow) * KVW + g * HDIM + csel * 4;
    const float* vsrc = Vtg + ((size_t)((b * NGROUP + g) * HDIM + srow)) * SEQ + csel * 4;
    uint32_t dOff[4];
#pragma unroll
    for (int i = 0; i < 4; i++)
        dOff[i] = (uint32_t)srow * 256 + ((uint32_t)((4 * i + csel) ^ (srow & 7)) << 4);

    const uint32_t rown  = (uint32_t)((lane & 7) + ((grp >> 1) << 3));
    const uint32_t rterm = rown * 256;
    const uint32_t r7    = rown & 7;
    const uint32_t cbit  = (uint32_t)(grp & 1);

    const int L0 = r0 * 4 + (a4 >> 1), L1 = L0 + 2;
    const bool pOdd = (a4 & 1) != 0;

    uint32_t qf[8][4];
    {
        const float sc = 0.125f;
        const float* qp = Q + (size_t)(b * SEQ + qt * 128 + w * 16) * HIDDEN + h * HDIM;
#pragma unroll
        for (int kc = 0; kc < 8; kc++) {
            const int c = kc * 8 + a4;
            qf[kc][0] = f2tf32(qp[(size_t)r0 * HIDDEN + c] * sc);
            qf[kc][1] = f2tf32(qp[(size_t)(r0 + 8) * HIDDEN + c] * sc);
            qf[kc][2] = f2tf32(qp[(size_t)r0 * HIDDEN + c + 4] * sc);
            qf[kc][3] = f2tf32(qp[(size_t)(r0 + 8) * HIDDEN + c + 4] * sc);
        }
    }

    float o[8][4];
#pragma unroll
    for (int nt = 0; nt < 8; nt++) {
        o[nt][0] = 0.f; o[nt][1] = 0.f; o[nt][2] = 0.f; o[nt][3] = 0.f;
    }
    float mi0 = -1e30f, mi1 = -1e30f, l0s = 0.f, l1s = 0.f;

    const int ktEnd = 2 * qt + 1;

#pragma unroll
    for (int t = 0; t < 2; t++) {
        const uint32_t buf = sb + t * ASTG;
        const float* kp = ksrc + (size_t)t * 64 * KVW;
        const float* vp = vsrc + t * 64;
#pragma unroll
        for (int i = 0; i < 4; i++) {
            cp16(buf + dOff[i],        kp + i * 16);
            cp16(buf + KSTG + dOff[i], vp + i * 16);
        }
        CP_COMMIT();
    }

    int cur = 0;
    for (int kt = 0; kt <= ktEnd; kt++) {
        CP_WAIT1();
        __syncthreads();

        if (kt + 2 <= ktEnd) {
            int nb = cur + 2; if (nb >= 3) nb -= 3;
            const uint32_t buf = sb + nb * ASTG;
            const float* kp = ksrc + (size_t)(kt + 2) * 64 * KVW;
            const float* vp = vsrc + (kt + 2) * 64;
#pragma unroll
            for (int i = 0; i < 4; i++) {
                cp16(buf + dOff[i],        kp + i * 16);
                cp16(buf + KSTG + dOff[i], vp + i * 16);
            }
        }
        CP_COMMIT();

        const uint32_t kbuf = sb + cur * ASTG;
        const uint32_t vbuf = kbuf + KSTG;

        float s[8][4];
#pragma unroll
        for (int nt = 0; nt < 8; nt++) {
            s[nt][0] = 0.f; s[nt][1] = 0.f; s[nt][2] = 0.f; s[nt][3] = 0.f;
        }
#pragma unroll
        for (int kc = 0; kc < 8; kc++) {
            const uint32_t kk = ((((uint32_t)(kc << 1)) | cbit) ^ r7) << 4;
#pragma unroll
            for (int nt2 = 0; nt2 < 4; nt2++) {
                uint32_t bf[4];
                ldsm_x4(bf, kbuf + nt2 * 4096 + rterm + kk);
                mma_tf32(s[2 * nt2],     qf[kc], bf[0], bf[1]);
                mma_tf32(s[2 * nt2 + 1], qf[kc], bf[2], bf[3]);
            }
        }

        if (kt >= 2 * qt) {
            const int diff  = (kt - 2 * qt) * 64;
            const int row0g = w * 16 + r0, row1g = row0g + 8;
#pragma unroll
            for (int nt = 0; nt < 8; nt++) {
                const int c0 = nt * 8 + 2 * a4 + diff, c1 = c0 + 1;
                if (c0 > row0g) s[nt][0] = -1e30f;
                if (c1 > row0g) s[nt][1] = -1e30f;
                if (c0 > row1g) s[nt][2] = -1e30f;
                if (c1 > row1g) s[nt][3] = -1e30f;
            }
        }

        float mx0 = -1e30f, mx1 = -1e30f;
#pragma unroll
        for (int nt = 0; nt < 8; nt++) {
            mx0 = fmaxf(mx0, fmaxf(s[nt][0], s[nt][1]));
            mx1 = fmaxf(mx1, fmaxf(s[nt][2], s[nt][3]));
        }
        mx0 = fmaxf(mx0, __shfl_xor_sync(0xffffffffu, mx0, 1));
        mx0 = fmaxf(mx0, __shfl_xor_sync(0xffffffffu, mx0, 2));
        mx1 = fmaxf(mx1, __shfl_xor_sync(0xffffffffu, mx1, 1));
        mx1 = fmaxf(mx1, __shfl_xor_sync(0xffffffffu, mx1, 2));
        const float nm0 = fmaxf(mi0, mx0), nm1 = fmaxf(mi1, mx1);
        const float cr0 = __expf(mi0 - nm0), cr1 = __expf(mi1 - nm1);
        float sum0 = 0.f, sum1 = 0.f;
#pragma unroll
        for (int nt = 0; nt < 8; nt++) {
            s[nt][0] = __expf(s[nt][0] - nm0);
            s[nt][1] = __expf(s[nt][1] - nm0);
            s[nt][2] = __expf(s[nt][2] - nm1);
            s[nt][3] = __expf(s[nt][3] - nm1);
            sum0 += s[nt][0] + s[nt][1];
            sum1 += s[nt][2] + s[nt][3];
        }
        sum0 += __shfl_xor_sync(0xffffffffu, sum0, 1);
        sum0 += __shfl_xor_sync(0xffffffffu, sum0, 2);
        sum1 += __shfl_xor_sync(0xffffffffu, sum1, 1);
        sum1 += __shfl_xor_sync(0xffffffffu, sum1, 2);
        l0s = l0s * cr0 + sum0;  l1s = l1s * cr1 + sum1;
        mi0 = nm0;               mi1 = nm1;
#pragma unroll
        for (int nt = 0; nt < 8; nt++) {
            o[nt][0] *= cr0; o[nt][1] *= cr0;
            o[nt][2] *= cr1; o[nt][3] *= cr1;
        }

#pragma unroll
        for (int kc = 0; kc < 8; kc++) {
            uint32_t pa[4];
            {
                float v0 = __shfl_sync(0xffffffffu, s[kc][0], L0);
                float v1 = __shfl_sync(0xffffffffu, s[kc][1], L0);
                pa[0] = f2tf32(pOdd ? v1 : v0);
                float v2 = __shfl_sync(0xffffffffu, s[kc][2], L0);
                float v3 = __shfl_sync(0xffffffffu, s[kc][3], L0);
                pa[1] = f2tf32(pOdd ? v3 : v2);
                v0 = __shfl_sync(0xffffffffu, s[kc][0], L1);
                v1 = __shfl_sync(0xffffffffu, s[kc][1], L1);
                pa[2] = f2tf32(pOdd ? v1 : v0);
                v2 = __shfl_sync(0xffffffffu, s[kc][2], L1);
                v3 = __shfl_sync(0xffffffffu, s[kc][3], L1);
                pa[3] = f2tf32(pOdd ? v3 : v2);
            }
            const uint32_t kk = ((((uint32_t)(kc << 1)) | cbit) ^ r7) << 4;
#pragma unroll
            for (int nt2 = 0; nt2 < 4; nt2++) {
                uint32_t bf[4];
                ldsm_x4(bf, vbuf + nt2 * 4096 + rterm + kk);
                mma_tf32(o[2 * nt2],     pa, bf[0], bf[1]);
                mma_tf32(o[2 * nt2 + 1], pa, bf[2], bf[3]);
            }
        }

        cur++; if (cur == 3) cur = 0;
    }

    const float inv0 = 1.f / l0s, inv1 = 1.f / l1s;
    const size_t row0 = (size_t)(b * SEQ + qt * 128 + w * 16 + r0);
#pragma unroll
    for (int nt = 0; nt < 8; nt++) {
        const int col = h * HDIM + nt * 8 + 2 * a4;
        *(float2*)&Out[row0 * HIDDEN + col] = make_float2(
            __uint_as_float(f2tf32(o[nt][0] * inv0)),
            __uint_as_float(f2tf32(o[nt][1] * inv0)));
        *(float2*)&Out[(row0 + 8) * HIDDEN + col] = make_float2(
            __uint_as_float(f2tf32(o[nt][2] * inv1)),
            __uint_as_float(f2tf32(o[nt][3] * inv1)));
    }
}

/* ================================================================= */
extern "C" void kernel_launch(void* const* d_in, const int* in_sizes, int n_in,
                              void* d_out, int out_size)
{
    (void)in_sizes; (void)n_in; (void)out_size;
    const float* x  = (const float*)d_in[0];
    /* d_in[1] = causal mask, handled analytically */
    const float* Wq = (const float*)d_in[2];
    const float* bq = (const float*)d_in[3];
    const float* Wk = (const float*)d_in[4];
    const float* bk = (const float*)d_in[5];
    const float* Wv = (const float*)d_in[6];
    const float* bv = (const float*)d_in[7];
    const float* Wo = (const float*)d_in[8];
    const float* bo = (const float*)d_in[9];
    float* out = (float*)d_out;

    float *q, *k, *vt, *attn;
    cudaGetSymbolAddress((void**)&q,    g_q);
    cudaGetSymbolAddress((void**)&k,    g_k);
    cudaGetSymbolAddress((void**)&vt,   g_vt);
    cudaGetSymbolAddress((void**)&attn, g_attn);

    cudaFuncSetAttribute(qkv_gemm, cudaFuncAttributeMaxDynamicSharedMemorySize, GEMM_SMEM);
    cudaFuncSetAttribute(oproj_sk, cudaFuncAttributeMaxDynamicSharedMemorySize, GEMM_SMEM);
    cudaFuncSetAttribute(attn_tc,  cudaFuncAttributeMaxDynamicSharedMemorySize, ATT_SMEM);

    /* 1. convert inputs to tf32 bits */
    cvt_all<<<2048, 256>>>((const float4*)x, (const float4*)Wq,
                           (const float4*)Wk, (const float4*)Wv,
                           (const float4*)Wo);

    /* 2. fused Q/K/V projection (K tf32, V tf32-transposed) */
    qkv_gemm<<<dim3(24, 16), 128, GEMM_SMEM>>>(bq, bk, bv);

    /* 3. causal GQA attention */
    attn_tc<<<dim3(SEQ / 128, NHEADS, BATCH), 256, ATT_SMEM>>>(q, k, vt, attn);

    /* 4. output projection: spin-synchronized split-K=2 */
    oproj_sk<<<dim3(16, 16, 2), 128, GEMM_SMEM>>>(bo, out);
}

// round 11
// speedup vs baseline: 1.3799x; 1.3799x over previous
#include <cuda_runtime.h>
#include <math.h>
#include <stdint.h>

#define HIDDEN 2048
#define SEQ    1024
#define BATCH  2
#define NHEADS 32
#define NGROUP 8
#define HDIM   64
#define MTOT   (BATCH * SEQ)
#define KVW    (NGROUP * HDIM)    /* 512  */
#define QKVW   (HIDDEN + 2 * KVW) /* 3072 */

/* ---------------- scratch (no cudaMalloc allowed) ---------------- */
__device__ float g_xt [MTOT * HIDDEN];               /* tf32 bits of x */
__device__ float g_wt [QKVW * HIDDEN];               /* Wq|Wk|Wv tf32  */
__device__ float g_wot[HIDDEN * HIDDEN];             /* Wo tf32        */
__device__ float g_q  [MTOT * HIDDEN];               /* fp32           */
__device__ float g_k  [MTOT * KVW];                  /* tf32 bits      */
__device__ float g_vt [BATCH * NGROUP * HDIM * SEQ]; /* tf32, [b,g,d,s]*/
__device__ float g_attn[MTOT * HIDDEN];              /* tf32 bits      */

/* ---------------- helpers ---------------- */
__device__ __forceinline__ uint32_t f2tf32(float x) {
    uint32_t r;
    asm("cvt.rna.tf32.f32 %0, %1;" : "=r"(r) : "f"(x));
    return r;
}
__device__ __forceinline__ uint32_t smem_u32(const void* p) {
    uint32_t a;
    asm("{ .reg .u64 t; cvta.to.shared.u64 t, %1; cvt.u32.u64 %0, t; }"
        : "=r"(a) : "l"(p));
    return a;
}
__device__ __forceinline__ void mma_tf32(float* c, const uint32_t* a,
                                         uint32_t b0, uint32_t b1) {
    asm volatile(
        "mma.sync.aligned.m16n8k8.row.col.f32.tf32.tf32.f32 "
        "{%0,%1,%2,%3}, {%4,%5,%6,%7}, {%8,%9}, {%0,%1,%2,%3};"
        : "+f"(c[0]), "+f"(c[1]), "+f"(c[2]), "+f"(c[3])
        : "r"(a[0]), "r"(a[1]), "r"(a[2]), "r"(a[3]), "r"(b0), "r"(b1));
}
__device__ __forceinline__ void ldsm_x4(uint32_t* r, uint32_t addr) {
    asm volatile("ldmatrix.sync.aligned.m8n8.x4.shared.b16 {%0,%1,%2,%3}, [%4];"
        : "=r"(r[0]), "=r"(r[1]), "=r"(r[2]), "=r"(r[3]) : "r"(addr));
}
__device__ __forceinline__ void cp16(uint32_t dst, const void* src) {
    asm volatile("cp.async.cg.shared.global [%0], [%1], 16;"
                 :: "r"(dst), "l"(src));
}
#define CP_COMMIT() asm volatile("cp.async.commit_group;" ::: "memory")
#define CP_WAIT0()  asm volatile("cp.async.wait_group 0;"  ::: "memory")
#define CP_WAIT1()  asm volatile("cp.async.wait_group 1;"  ::: "memory")

/* =================================================================
 * Pre-convert x, Wq|Wk|Wv, Wo to tf32 bits (grid-stride, float4).
 * ================================================================= */
__global__ void cvt_all(const float4* __restrict__ x,
                        const float4* __restrict__ wq,
                        const float4* __restrict__ wk,
                        const float4* __restrict__ wv,
                        const float4* __restrict__ wo)
{
    const int64_t N0 = 1048576;
    const int64_t N1 = N0 + 1048576;
    const int64_t N2 = N1 + 262144;
    const int64_t N3 = N2 + 262144;
    const int64_t N4 = N3 + 1048576;
    uint4* xt  = (uint4*)g_xt;
    uint4* wt  = (uint4*)g_wt;
    uint4* wot = (uint4*)g_wot;
    for (int64_t i = (int64_t)blockIdx.x * blockDim.x + threadIdx.x;
         i < N4; i += (int64_t)gridDim.x * blockDim.x) {
        float4 v; uint4* dst;
        if (i < N0)      { v = x [i];      dst = xt  + i; }
        else if (i < N1) { v = wq[i - N0]; dst = wt  + (i - N0); }
        else if (i < N2) { v = wk[i - N1]; dst = wt  + 1048576 + (i - N1); }
        else if (i < N3) { v = wv[i - N2]; dst = wt  + 1310720 + (i - N2); }
        else             { v = wo[i - N3]; dst = wot + (i - N3); }
        uint4 u;
        u.x = f2tf32(v.x); u.y = f2tf32(v.y);
        u.z = f2tf32(v.z); u.w = f2tf32(v.w);
        *dst = u;
    }
}

/* =================================================================
 * TF32 NT GEMM core: CTA 128x64, 128 threads (4 warps 2x2),
 * warp tile 64x32, BK=32, cp.async double-buffered, XOR-swizzled
 * 128B rows. 48KB smem -> 4 CTAs/SM (16 warps).
 * MODE: 0 fp32+bias | 1 tf32+bias | 2 tf32+bias transposed to g_vt.
 * ================================================================= */
#define BK     32
#define TILEA  16384                   /* 128 rows x 128 B */
#define TILEBB 8192                    /*  64 rows x 128 B */
#define STAGE  (TILEA + TILEBB)        /* 24576 */
#define GEMM_SMEM (2 * STAGE)          /* 49152 */

template<int MODE>
__device__ __forceinline__ void gemm_core(
    const float* __restrict__ A, const float* __restrict__ Bm,
    const float* __restrict__ bias, float* __restrict__ C,
    int ldc, int K, int m0, int n0B, int n0C)
{
    extern __shared__ char smem[];
    const uint32_t sb = smem_u32(smem);
    const int tid = threadIdx.x, lane = tid & 31, wid = tid >> 5;
    const int wm = (wid & 1) * 64, wn = (wid >> 1) * 32;
    const int grp = lane >> 3;

    const uint32_t xm   = (uint32_t)(lane & 7) << 4;
    const uint32_t rowA = (uint32_t)(wm + (lane & 7) + ((grp & 1) << 3)) * 128;
    const uint32_t rowB = (uint32_t)(wn + (lane & 7) + ((grp >> 1) << 3)) * 128;
    const uint32_t cA   = (uint32_t)(grp >> 1) << 4;
    const uint32_t cB   = (uint32_t)(grp & 1) << 4;

    float acc[4][4][4];
#pragma unroll
    for (int mt = 0; mt < 4; mt++)
#pragma unroll
        for (int nt = 0; nt < 4; nt++) {
            acc[mt][nt][0] = 0.f; acc[mt][nt][1] = 0.f;
            acc[mt][nt][2] = 0.f; acc[mt][nt][3] = 0.f;
        }

    /* loaders: A row = tid (8 chunks); B row = tid>>1 (4 chunks) */
    const float* Ag = A  + (size_t)(m0 + tid) * K;
    const int   brow = tid >> 1, bc4 = (tid & 1) * 4;
    const float* Bg = Bm + (size_t)(n0B + brow) * K + bc4 * 4;
    const uint32_t aRow = (uint32_t)tid * 128;
    const uint32_t aX   = (uint32_t)(tid & 7) << 4;
    const uint32_t bRow = (uint32_t)brow * 128;
    const uint32_t bX7  = (uint32_t)(brow & 7);
    const int nIter = K / BK;

    /* prologue: stage 0 */
#pragma unroll
    for (int i = 0; i < 8; i++)
        cp16(sb + aRow + (((uint32_t)i << 4) ^ aX), Ag + i * 4);
#pragma unroll
    for (int i = 0; i < 4; i++)
        cp16(sb + TILEA + bRow + (((uint32_t)(bc4 + i) ^ bX7) << 4), Bg + i * 4);
    CP_COMMIT();

    for (int it = 0; it < nIter; it++) {
        CP_WAIT0();
        __syncthreads();

        const uint32_t aB = sb + (it & 1) * STAGE;
        const uint32_t bB = aB + TILEA;
        const uint32_t nx = sb + ((it + 1) & 1) * STAGE;
        const bool pf = (it + 1 < nIter);
        const float* Ap = Ag + (it + 1) * BK;
        const float* Bp = Bg + (it + 1) * BK;

#pragma unroll
        for (int ks = 0; ks < 4; ks++) {
            /* scatter prefetch: 2 A chunks + 1 B chunk per ks */
            if (pf) {
                cp16(nx + aRow + ((((uint32_t)(2 * ks) << 4))     ^ aX),
                     Ap + (2 * ks) * 4);
                cp16(nx + aRow + ((((uint32_t)(2 * ks + 1) << 4)) ^ aX),
                     Ap + (2 * ks + 1) * 4);
                cp16(nx + TILEA + bRow + (((uint32_t)(bc4 + ks) ^ bX7) << 4),
                     Bp + ks * 4);
            }
            const uint32_t ck = ((uint32_t)ks << 5);
            uint32_t af[4][4];
#pragma unroll
            for (int mt = 0; mt < 4; mt++)
                ldsm_x4(af[mt], aB + rowA + mt * 2048 + ((ck + cA) ^ xm));
            uint32_t bf[2][4];
            ldsm_x4(bf[0], bB + rowB + ((ck + cB) ^ xm));
            ldsm_x4(bf[1], bB + rowB + 2048 + ((ck + cB) ^ xm));
#pragma unroll
            for (int nb = 0; nb < 2; nb++) {
#pragma unroll
                for (int mt = 0; mt < 4; mt++) {
                    mma_tf32(acc[mt][2 * nb],     af[mt], bf[nb][0], bf[nb][1]);
                    mma_tf32(acc[mt][2 * nb + 1], af[mt], bf[nb][2], bf[nb][3]);
                }
            }
        }
        CP_COMMIT();
    }

    const int r0 = lane >> 2, a4 = lane & 3;
#pragma unroll
    for (int mt = 0; mt < 4; mt++) {
#pragma unroll
        for (int nt = 0; nt < 4; nt++) {
            const int col = n0C + wn + nt * 8 + 2 * a4;
            const float b0 = bias[col], b1 = bias[col + 1];
            const int rA = m0 + wm + mt * 16 + r0;
            if (MODE == 0) {
                *(float2*)&C[(size_t)rA * ldc + col] =
                    make_float2(acc[mt][nt][0] + b0, acc[mt][nt][1] + b1);
                *(float2*)&C[(size_t)(rA + 8) * ldc + col] =
                    make_float2(acc[mt][nt][2] + b0, acc[mt][nt][3] + b1);
            } else if (MODE == 1) {
                *(float2*)&C[(size_t)rA * ldc + col] = make_float2(
                    __uint_as_float(f2tf32(acc[mt][nt][0] + b0)),
                    __uint_as_float(f2tf32(acc[mt][nt][1] + b1)));
                *(float2*)&C[(size_t)(rA + 8) * ldc + col] = make_float2(
                    __uint_as_float(f2tf32(acc[mt][nt][2] + b0)),
                    __uint_as_float(f2tf32(acc[mt][nt][3] + b1)));
            } else {
                /* transposed tf32 store into g_vt[b,g,d,s] */
                const int r1 = rA + 8;
#pragma unroll
                for (int q = 0; q < 2; q++) {
                    const int r = q ? r1 : rA;
                    const size_t base =
                        ((size_t)((r >> 10) * 8 + (col >> 6)) * 64) * 1024
                        + (size_t)(r & 1023);
                    g_vt[base + (size_t)(col & 63) * 1024] =
                        __uint_as_float(f2tf32(acc[mt][nt][2 * q] + b0));
                    g_vt[base + (size_t)((col & 63) + 1) * 1024] =
                        __uint_as_float(f2tf32(acc[mt][nt][2 * q + 1] + b1));
                }
            }
        }
    }
}

/* fused QKV projection: grid (48, 16) — N tiles of 64 */
__global__ __launch_bounds__(128, 4) void qkv_gemm(
    const float* __restrict__ bq, const float* __restrict__ bk,
    const float* __restrict__ bv)
{
    const int n0 = blockIdx.x * 64, m0 = blockIdx.y * 128;
    if (n0 < 2048)
        gemm_core<0>(g_xt, g_wt, bq, g_q, HIDDEN, HIDDEN, m0, n0, n0);
    else if (n0 < 2560)
        gemm_core<1>(g_xt, g_wt, bk, g_k, KVW, HIDDEN, m0, n0, n0 - 2048);
    else
        gemm_core<2>(g_xt, g_wt, bv, (float*)0, KVW, HIDDEN, m0, n0, n0 - 2560);
}

/* O projection: grid (32, 16) */
__global__ __launch_bounds__(128, 4) void oproj_gemm(
    const float* __restrict__ bo, float* __restrict__ out)
{
    gemm_core<0>(g_attn, g_wot, bo, out, HIDDEN, HIDDEN,
                 blockIdx.y * 128, blockIdx.x * 64, blockIdx.x * 64);
}

/* =================================================================
 * Flash attention (causal, GQA): 128 q-rows/CTA, 256 thr, 8 warps.
 * K/V staged via cp.async (V pre-transposed tf32); P in registers
 * via lane-shuffle C-frag -> A-frag conversion. 1 barrier per tile.
 * ================================================================= */
#define KSTG  16384                    /* 64 rows x 256 B */
#define ASTG  (2 * KSTG)
#define ATT_SMEM (3 * ASTG)            /* 98304 */

__global__ __launch_bounds__(256, 2) void attn_tc(
    const float* __restrict__ Q, const float* __restrict__ Kp,
    const float* __restrict__ Vtg, float* __restrict__ Out)
{
    extern __shared__ char smA[];
    const uint32_t sb = smem_u32(smA);

    const int qt = (int)gridDim.x - 1 - (int)blockIdx.x;  /* longest first */
    const int h = blockIdx.y, b = blockIdx.z, g = h >> 2;
    const int tid = threadIdx.x, lane = tid & 31, w = tid >> 5;
    const int r0 = lane >> 2, a4 = lane & 3;
    const int grp = lane >> 3;

    const int srow = tid >> 2, csel = tid & 3;
    const float* ksrc = Kp  + ((size_t)(b * SEQ) + srow) * KVW + g * HDIM + csel * 4;
    const float* vsrc = Vtg + ((size_t)((b * NGROUP + g) * HDIM + srow)) * SEQ + csel * 4;
    uint32_t dOff[4];
#pragma unroll
    for (int i = 0; i < 4; i++)
        dOff[i] = (uint32_t)srow * 256 + ((uint32_t)((4 * i + csel) ^ (srow & 7)) << 4);

    const uint32_t rown  = (uint32_t)((lane & 7) + ((grp >> 1) << 3));
    const uint32_t rterm = rown * 256;
    const uint32_t r7    = rown & 7;
    const uint32_t cbit  = (uint32_t)(grp & 1);

    const int L0 = r0 * 4 + (a4 >> 1), L1 = L0 + 2;
    const bool pOdd = (a4 & 1) != 0;

    uint32_t qf[8][4];
    {
        const float sc = 0.125f;
        const float* qp = Q + (size_t)(b * SEQ + qt * 128 + w * 16) * HIDDEN + h * HDIM;
#pragma unroll
        for (int kc = 0; kc < 8; kc++) {
            const int c = kc * 8 + a4;
            qf[kc][0] = f2tf32(qp[(size_t)r0 * HIDDEN + c] * sc);
            qf[kc][1] = f2tf32(qp[(size_t)(r0 + 8) * HIDDEN + c] * sc);
            qf[kc][2] = f2tf32(qp[(size_t)r0 * HIDDEN + c + 4] * sc);
            qf[kc][3] = f2tf32(qp[(size_t)(r0 + 8) * HIDDEN + c + 4] * sc);
        }
    }

    float o[8][4];
#pragma unroll
    for (int nt = 0; nt < 8; nt++) {
        o[nt][0] = 0.f; o[nt][1] = 0.f; o[nt][2] = 0.f; o[nt][3] = 0.f;
    }
    float mi0 = -1e30f, mi1 = -1e30f, l0s = 0.f, l1s = 0.f;

    const int ktEnd = 2 * qt + 1;

#pragma unroll
    for (int t = 0; t < 2; t++) {
        const uint32_t buf = sb + t * ASTG;
        const float* kp = ksrc + (size_t)t * 64 * KVW;
        const float* vp = vsrc + t * 64;
#pragma unroll
        for (int i = 0; i < 4; i++) {
            cp16(buf + dOff[i],        kp + i * 16);
            cp16(buf + KSTG + dOff[i], vp + i * 16);
        }
        CP_COMMIT();
    }

    int cur = 0;
    for (int kt = 0; kt <= ktEnd; kt++) {
        CP_WAIT1();
        __syncthreads();

        if (kt + 2 <= ktEnd) {
            int nb = cur + 2; if (nb >= 3) nb -= 3;
            const uint32_t buf = sb + nb * ASTG;
            const float* kp = ksrc + (size_t)(kt + 2) * 64 * KVW;
            const float* vp = vsrc + (kt + 2) * 64;
#pragma unroll
            for (int i = 0; i < 4; i++) {
                cp16(buf + dOff[i],        kp + i * 16);
                cp16(buf + KSTG + dOff[i], vp + i * 16);
            }
        }
        CP_COMMIT();

        const uint32_t kbuf = sb + cur * ASTG;
        const uint32_t vbuf = kbuf + KSTG;

        float s[8][4];
#pragma unroll
        for (int nt = 0; nt < 8; nt++) {
            s[nt][0] = 0.f; s[nt][1] = 0.f; s[nt][2] = 0.f; s[nt][3] = 0.f;
        }
#pragma unroll
        for (int kc = 0; kc < 8; kc++) {
            const uint32_t kk = ((((uint32_t)(kc << 1)) | cbit) ^ r7) << 4;
#pragma unroll
            for (int nt2 = 0; nt2 < 4; nt2++) {
                uint32_t bf[4];
                ldsm_x4(bf, kbuf + nt2 * 4096 + rterm + kk);
                mma_tf32(s[2 * nt2],     qf[kc], bf[0], bf[1]);
                mma_tf32(s[2 * nt2 + 1], qf[kc], bf[2], bf[3]);
            }
        }

        if (kt >= 2 * qt) {
            const int diff  = (kt - 2 * qt) * 64;
            const int row0g = w * 16 + r0, row1g = row0g + 8;
#pragma unroll
            for (int nt = 0; nt < 8; nt++) {
                const int c0 = nt * 8 + 2 * a4 + diff, c1 = c0 + 1;
                if (c0 > row0g) s[nt][0] = -1e30f;
                if (c1 > row0g) s[nt][1] = -1e30f;
                if (c0 > row1g) s[nt][2] = -1e30f;
                if (c1 > row1g) s[nt][3] = -1e30f;
            }
        }

        float mx0 = -1e30f, mx1 = -1e30f;
#pragma unroll
        for (int nt = 0; nt < 8; nt++) {
            mx0 = fmaxf(mx0, fmaxf(s[nt][0], s[nt][1]));
            mx1 = fmaxf(mx1, fmaxf(s[nt][2], s[nt][3]));
        }
        mx0 = fmaxf(mx0, __shfl_xor_sync(0xffffffffu, mx0, 1));
        mx0 = fmaxf(mx0, __shfl_xor_sync(0xffffffffu, mx0, 2));
        mx1 = fmaxf(mx1, __shfl_xor_sync(0xffffffffu, mx1, 1));
        mx1 = fmaxf(mx1, __shfl_xor_sync(0xffffffffu, mx1, 2));
        const float nm0 = fmaxf(mi0, mx0), nm1 = fmaxf(mi1, mx1);
        const float cr0 = __expf(mi0 - nm0), cr1 = __expf(mi1 - nm1);
        float sum0 = 0.f, sum1 = 0.f;
#pragma unroll
        for (int nt = 0; nt < 8; nt++) {
            s[nt][0] = __expf(s[nt][0] - nm0);
            s[nt][1] = __expf(s[nt][1] - nm0);
            s[nt][2] = __expf(s[nt][2] - nm1);
            s[nt][3] = __expf(s[nt][3] - nm1);
            sum0 += s[nt][0] + s[nt][1];
            sum1 += s[nt][2] + s[nt][3];
        }
        sum0 += __shfl_xor_sync(0xffffffffu, sum0, 1);
        sum0 += __shfl_xor_sync(0xffffffffu, sum0, 2);
        sum1 += __shfl_xor_sync(0xffffffffu, sum1, 1);
        sum1 += __shfl_xor_sync(0xffffffffu, sum1, 2);
        l0s = l0s * cr0 + sum0;  l1s = l1s * cr1 + sum1;
        mi0 = nm0;               mi1 = nm1;
#pragma unroll
        for (int nt = 0; nt < 8; nt++) {
            o[nt][0] *= cr0; o[nt][1] *= cr0;
            o[nt][2] *= cr1; o[nt][3] *= cr1;
        }

#pragma unroll
        for (int kc = 0; kc < 8; kc++) {
            uint32_t pa[4];
            {
                float v0 = __shfl_sync(0xffffffffu, s[kc][0], L0);
                float v1 = __shfl_sync(0xffffffffu, s[kc][1], L0);
                pa[0] = f2tf32(pOdd ? v1 : v0);
                float v2 = __shfl_sync(0xffffffffu, s[kc][2], L0);
                float v3 = __shfl_sync(0xffffffffu, s[kc][3], L0);
                pa[1] = f2tf32(pOdd ? v3 : v2);
                v0 = __shfl_sync(0xffffffffu, s[kc][0], L1);
                v1 = __shfl_sync(0xffffffffu, s[kc][1], L1);
                pa[2] = f2tf32(pOdd ? v1 : v0);
                v2 = __shfl_sync(0xffffffffu, s[kc][2], L1);
                v3 = __shfl_sync(0xffffffffu, s[kc][3], L1);
                pa[3] = f2tf32(pOdd ? v3 : v2);
            }
            const uint32_t kk = ((((uint32_t)(kc << 1)) | cbit) ^ r7) << 4;
#pragma unroll
            for (int nt2 = 0; nt2 < 4; nt2++) {
                uint32_t bf[4];
                ldsm_x4(bf, vbuf + nt2 * 4096 + rterm + kk);
                mma_tf32(o[2 * nt2],     pa, bf[0], bf[1]);
                mma_tf32(o[2 * nt2 + 1], pa, bf[2], bf[3]);
            }
        }

        cur++; if (cur == 3) cur = 0;
    }

    const float inv0 = 1.f / l0s, inv1 = 1.f / l1s;
    const size_t row0 = (size_t)(b * SEQ + qt * 128 + w * 16 + r0);
#pragma unroll
    for (int nt = 0; nt < 8; nt++) {
        const int col = h * HDIM + nt * 8 + 2 * a4;
        *(float2*)&Out[row0 * HIDDEN + col] = make_float2(
            __uint_as_float(f2tf32(o[nt][0] * inv0)),
            __uint_as_float(f2tf32(o[nt][1] * inv0)));
        *(float2*)&Out[(row0 + 8) * HIDDEN + col] = make_float2(
            __uint_as_float(f2tf32(o[nt][2] * inv1)),
            __uint_as_float(f2tf32(o[nt][3] * inv1)));
    }
}

/* ================================================================= */
extern "C" void kernel_launch(void* const* d_in, const int* in_sizes, int n_in,
                              void* d_out, int out_size)
{
    (void)in_sizes; (void)n_in; (void)out_size;
    const float* x  = (const float*)d_in[0];
    /* d_in[1] = causal mask, handled analytically */
    const float* Wq = (const float*)d_in[2];
    const float* bq = (const float*)d_in[3];
    const float* Wk = (const float*)d_in[4];
    const float* bk = (const float*)d_in[5];
    const float* Wv = (const float*)d_in[6];
    const float* bv = (const float*)d_in[7];
    const float* Wo = (const float*)d_in[8];
    const float* bo = (const float*)d_in[9];
    float* out = (float*)d_out;

    float *q, *k, *vt, *attn;
    cudaGetSymbolAddress((void**)&q,    g_q);
    cudaGetSymbolAddress((void**)&k,    g_k);
    cudaGetSymbolAddress((void**)&vt,   g_vt);
    cudaGetSymbolAddress((void**)&attn, g_attn);

    cudaFuncSetAttribute(qkv_gemm,   cudaFuncAttributeMaxDynamicSharedMemorySize, GEMM_SMEM);
    cudaFuncSetAttribute(oproj_gemm, cudaFuncAttributeMaxDynamicSharedMemorySize, GEMM_SMEM);
    cudaFuncSetAttribute(attn_tc,    cudaFuncAttributeMaxDynamicSharedMemorySize, ATT_SMEM);

    /* 1. convert inputs to tf32 bits */
    cvt_all<<<2048, 256>>>((const float4*)x, (const float4*)Wq,
                           (const float4*)Wk, (const float4*)Wv,
                           (const float4*)Wo);

    /* 2. fused Q/K/V projection (K tf32, V tf32-transposed) */
    qkv_gemm<<<dim3(48, 16), 128, GEMM_SMEM>>>(bq, bk, bv);

    /* 3. causal GQA attention */
    attn_tc<<<dim3(SEQ / 128, NHEADS, BATCH), 256, ATT_SMEM>>>(q, k, vt, attn);

    /* 4. output projection */
    oproj_gemm<<<dim3(32, 16), 128, GEMM_SMEM>>>(bo, out);
}

// round 12
// speedup vs baseline: 1.5933x; 1.1546x over previous
#include <cuda_runtime.h>
#include <math.h>
#include <stdint.h>

#define HIDDEN 2048
#define SEQ    1024
#define BATCH  2
#define NHEADS 32
#define NGROUP 8
#define HDIM   64
#define MTOT   (BATCH * SEQ)
#define KVW    (NGROUP * HDIM)    /* 512  */

/* ---------------- scratch (no cudaMalloc allowed) ---------------- */
__device__ float g_q  [MTOT * HIDDEN];               /* fp32           */
__device__ float g_k  [MTOT * KVW];                  /* tf32 bits      */
__device__ float g_vt [BATCH * NGROUP * HDIM * SEQ]; /* tf32, [b,g,d,s]*/
__device__ float g_attn[MTOT * HIDDEN];              /* tf32 bits      */

/* ---------------- helpers ---------------- */
__device__ __forceinline__ uint32_t f2tf32(float x) {
    uint32_t r;
    asm("cvt.rna.tf32.f32 %0, %1;" : "=r"(r) : "f"(x));
    return r;
}
__device__ __forceinline__ uint32_t u2tf32(uint32_t x) {
    uint32_t r;
    asm("cvt.rna.tf32.f32 %0, %1;" : "=r"(r) : "f"(__uint_as_float(x)));
    return r;
}
__device__ __forceinline__ uint32_t smem_u32(const void* p) {
    uint32_t a;
    asm("{ .reg .u64 t; cvta.to.shared.u64 t, %1; cvt.u32.u64 %0, t; }"
        : "=r"(a) : "l"(p));
    return a;
}
__device__ __forceinline__ void mma_tf32(float* c, const uint32_t* a,
                                         uint32_t b0, uint32_t b1) {
    asm volatile(
        "mma.sync.aligned.m16n8k8.row.col.f32.tf32.tf32.f32 "
        "{%0,%1,%2,%3}, {%4,%5,%6,%7}, {%8,%9}, {%0,%1,%2,%3};"
        : "+f"(c[0]), "+f"(c[1]), "+f"(c[2]), "+f"(c[3])
        : "r"(a[0]), "r"(a[1]), "r"(a[2]), "r"(a[3]), "r"(b0), "r"(b1));
}
__device__ __forceinline__ void ldsm_x4(uint32_t* r, uint32_t addr) {
    asm volatile("ldmatrix.sync.aligned.m8n8.x4.shared.b16 {%0,%1,%2,%3}, [%4];"
        : "=r"(r[0]), "=r"(r[1]), "=r"(r[2]), "=r"(r[3]) : "r"(addr));
}
__device__ __forceinline__ void cp16(uint32_t dst, const void* src) {
    asm volatile("cp.async.cg.shared.global [%0], [%1], 16;"
                 :: "r"(dst), "l"(src));
}
#define CP_COMMIT() asm volatile("cp.async.commit_group;" ::: "memory")
#define CP_WAIT0()  asm volatile("cp.async.wait_group 0;"  ::: "memory")
#define CP_WAIT1()  asm volatile("cp.async.wait_group 1;"  ::: "memory")

/* =================================================================
 * TF32 NT GEMM core (R9 config): CTA 128x128, 128 threads
 * (4 warps 2x2), warp tile 64x64, BK=32, cp.async double-buffered,
 * XOR-swizzled 128B rows, 64KB smem -> 3 CTAs/SM.
 * Fragments are raw fp32 from gmem; converted to tf32 IN REGISTERS
 * right after ldmatrix (bit-identical to pre-converted memory,
 * idempotent on already-tf32 data).
 * MODE: 0 fp32+bias | 1 tf32+bias | 2 tf32+bias transposed to g_vt.
 * ================================================================= */
#define BK    32
#define TILEB 16384
#define STAGE (2 * TILEB)
#define GEMM_SMEM (2 * STAGE)          /* 65536 */

template<int MODE>
__device__ __forceinline__ void gemm_core(
    const float* __restrict__ A, const float* __restrict__ Bm,
    const float* __restrict__ bias, float* __restrict__ C,
    int ldc, int K, int m0, int n0B, int n0C)
{
    extern __shared__ char smem[];
    const uint32_t sb = smem_u32(smem);
    const int tid = threadIdx.x, lane = tid & 31, wid = tid >> 5;
    const int wm = (wid & 1) * 64, wn = (wid >> 1) * 64;
    const int grp = lane >> 3;

    const uint32_t xm   = (uint32_t)(lane & 7) << 4;
    const uint32_t rowA = (uint32_t)(wm + (lane & 7) + ((grp & 1) << 3)) * 128;
    const uint32_t rowB = (uint32_t)(wn + (lane & 7) + ((grp >> 1) << 3)) * 128;
    const uint32_t cA   = (uint32_t)(grp >> 1) << 4;
    const uint32_t cB   = (uint32_t)(grp & 1) << 4;

    float acc[4][8][4];
#pragma unroll
    for (int mt = 0; mt < 4; mt++)
#pragma unroll
        for (int nt = 0; nt < 8; nt++) {
            acc[mt][nt][0] = 0.f; acc[mt][nt][1] = 0.f;
            acc[mt][nt][2] = 0.f; acc[mt][nt][3] = 0.f;
        }

    const float* Ag = A  + (size_t)(m0  + tid) * K;
    const float* Bg = Bm + (size_t)(n0B + tid) * K;
    const uint32_t sRow = (uint32_t)tid * 128;
    const uint32_t sX   = (uint32_t)(tid & 7) << 4;
    const int nIter = K / BK;

#pragma unroll
    for (int i = 0; i < 8; i++) {
        const uint32_t d = sRow + (((uint32_t)i << 4) ^ sX);
        cp16(sb + d,         Ag + i * 4);
        cp16(sb + TILEB + d, Bg + i * 4);
    }
    CP_COMMIT();

    for (int it = 0; it < nIter; it++) {
        CP_WAIT0();
        __syncthreads();

        const uint32_t aB = sb + (it & 1) * STAGE;
        const uint32_t bB = aB + TILEB;
        const uint32_t nx = sb + ((it + 1) & 1) * STAGE;
        const bool pf = (it + 1 < nIter);
        const float* Ap = Ag + (it + 1) * BK;
        const float* Bp = Bg + (it + 1) * BK;

#pragma unroll
        for (int ks = 0; ks < 4; ks++) {
            if (pf) {
                const uint32_t d0 = sRow + ((((uint32_t)(2 * ks) << 4))     ^ sX);
                const uint32_t d1 = sRow + ((((uint32_t)(2 * ks + 1) << 4)) ^ sX);
                cp16(nx + d0,         Ap + (2 * ks) * 4);
                cp16(nx + d1,         Ap + (2 * ks + 1) * 4);
                cp16(nx + TILEB + d0, Bp + (2 * ks) * 4);
                cp16(nx + TILEB + d1, Bp + (2 * ks + 1) * 4);
            }
            const uint32_t ck = ((uint32_t)ks << 5);
            uint32_t af[4][4];
#pragma unroll
            for (int mt = 0; mt < 4; mt++) {
                ldsm_x4(af[mt], aB + rowA + mt * 2048 + ((ck + cA) ^ xm));
                af[mt][0] = u2tf32(af[mt][0]); af[mt][1] = u2tf32(af[mt][1]);
                af[mt][2] = u2tf32(af[mt][2]); af[mt][3] = u2tf32(af[mt][3]);
            }
            uint32_t bf[2][4];
            ldsm_x4(bf[0], bB + rowB + ((ck + cB) ^ xm));
            bf[0][0] = u2tf32(bf[0][0]); bf[0][1] = u2tf32(bf[0][1]);
            bf[0][2] = u2tf32(bf[0][2]); bf[0][3] = u2tf32(bf[0][3]);
#pragma unroll
            for (int nt2 = 0; nt2 < 4; nt2++) {
                const int c = nt2 & 1, n = 1 - c;
                if (nt2 < 3) {
                    ldsm_x4(bf[n], bB + rowB + (nt2 + 1) * 2048 + ((ck + cB) ^ xm));
                    bf[n][0] = u2tf32(bf[n][0]); bf[n][1] = u2tf32(bf[n][1]);
                    bf[n][2] = u2tf32(bf[n][2]); bf[n][3] = u2tf32(bf[n][3]);
                }
#pragma unroll
                for (int mt = 0; mt < 4; mt++) {
                    mma_tf32(acc[mt][2 * nt2],     af[mt], bf[c][0], bf[c][1]);
                    mma_tf32(acc[mt][2 * nt2 + 1], af[mt], bf[c][2], bf[c][3]);
                }
            }
        }
        CP_COMMIT();
    }

    const int r0 = lane >> 2, a4 = lane & 3;
#pragma unroll
    for (int mt = 0; mt < 4; mt++) {
#pragma unroll
        for (int nt = 0; nt < 8; nt++) {
            const int col = n0C + wn + nt * 8 + 2 * a4;
            const float b0 = bias[col], b1 = bias[col + 1];
            const int rA = m0 + wm + mt * 16 + r0;
            if (MODE == 0) {
                *(float2*)&C[(size_t)rA * ldc + col] =
                    make_float2(acc[mt][nt][0] + b0, acc[mt][nt][1] + b1);
                *(float2*)&C[(size_t)(rA + 8) * ldc + col] =
                    make_float2(acc[mt][nt][2] + b0, acc[mt][nt][3] + b1);
            } else if (MODE == 1) {
                *(float2*)&C[(size_t)rA * ldc + col] = make_float2(
                    __uint_as_float(f2tf32(acc[mt][nt][0] + b0)),
                    __uint_as_float(f2tf32(acc[mt][nt][1] + b1)));
                *(float2*)&C[(size_t)(rA + 8) * ldc + col] = make_float2(
                    __uint_as_float(f2tf32(acc[mt][nt][2] + b0)),
                    __uint_as_float(f2tf32(acc[mt][nt][3] + b1)));
            } else {
                /* transposed tf32 store into g_vt[b,g,d,s] */
                const int r1 = rA + 8;
#pragma unroll
                for (int q = 0; q < 2; q++) {
                    const int r = q ? r1 : rA;
                    const size_t base =
                        ((size_t)((r >> 10) * 8 + (col >> 6)) * 64) * 1024
                        + (size_t)(r & 1023);
                    g_vt[base + (size_t)(col & 63) * 1024] =
                        __uint_as_float(f2tf32(acc[mt][nt][2 * q] + b0));
                    g_vt[base + (size_t)((col & 63) + 1) * 1024] =
                        __uint_as_float(f2tf32(acc[mt][nt][2 * q + 1] + b1));
                }
            }
        }
    }
}

/* fused QKV projection: grid (24, 16) */
__global__ __launch_bounds__(128, 3) void qkv_gemm(
    const float* __restrict__ x,
    const float* __restrict__ Wq, const float* __restrict__ bq,
    const float* __restrict__ Wk, const float* __restrict__ bk,
    const float* __restrict__ Wv, const float* __restrict__ bv)
{
    const int n0 = blockIdx.x * 128, m0 = blockIdx.y * 128;
    if (n0 < 2048)
        gemm_core<0>(x, Wq, bq, g_q, HIDDEN, HIDDEN, m0, n0, n0);
    else if (n0 < 2560)
        gemm_core<1>(x, Wk, bk, g_k, KVW, HIDDEN, m0, n0 - 2048, n0 - 2048);
    else
        gemm_core<2>(x, Wv, bv, (float*)0, KVW, HIDDEN, m0, n0 - 2560, n0 - 2560);
}

/* O projection: grid (16, 16) */
__global__ __launch_bounds__(128, 3) void oproj_gemm(
    const float* __restrict__ Wo, const float* __restrict__ bo,
    float* __restrict__ out)
{
    gemm_core<0>(g_attn, Wo, bo, out, HIDDEN, HIDDEN,
                 blockIdx.y * 128, blockIdx.x * 128, blockIdx.x * 128);
}

/* =================================================================
 * Flash attention (causal, GQA): 128 q-rows/CTA, 256 thr, 8 warps.
 * K/V staged via cp.async (V pre-transposed tf32); P in registers
 * via lane-shuffle C-frag -> A-frag conversion. 1 barrier per tile.
 * ================================================================= */
#define KSTG  16384                    /* 64 rows x 256 B */
#define ASTG  (2 * KSTG)
#define ATT_SMEM (3 * ASTG)            /* 98304 */

__global__ __launch_bounds__(256, 2) void attn_tc(
    const float* __restrict__ Q, const float* __restrict__ Kp,
    const float* __restrict__ Vtg, float* __restrict__ Out)
{
    extern __shared__ char smA[];
    const uint32_t sb = smem_u32(smA);

    const int qt = (int)gridDim.x - 1 - (int)blockIdx.x;  /* longest first */
    const int h = blockIdx.y, b = blockIdx.z, g = h >> 2;
    const int tid = threadIdx.x, lane = tid & 31, w = tid >> 5;
    const int r0 = lane >> 2, a4 = lane & 3;
    const int grp = lane >> 3;

    const int srow = tid >> 2, csel = tid & 3;
    const float* ksrc = Kp  + ((size_t)(b * SEQ) + srow) * KVW + g * HDIM + csel * 4;
    const float* vsrc = Vtg + ((size_t)((b * NGROUP + g) * HDIM + srow)) * SEQ + csel * 4;
    uint32_t dOff[4];
#pragma unroll
    for (int i = 0; i < 4; i++)
        dOff[i] = (uint32_t)srow * 256 + ((uint32_t)((4 * i + csel) ^ (srow & 7)) << 4);

    const uint32_t rown  = (uint32_t)((lane & 7) + ((grp >> 1) << 3));
    const uint32_t rterm = rown * 256;
    const uint32_t r7    = rown & 7;
    const uint32_t cbit  = (uint32_t)(grp & 1);

    const int L0 = r0 * 4 + (a4 >> 1), L1 = L0 + 2;
    const bool pOdd = (a4 & 1) != 0;

    uint32_t qf[8][4];
    {
        const float sc = 0.125f;
        const float* qp = Q + (size_t)(b * SEQ + qt * 128 + w * 16) * HIDDEN + h * HDIM;
#pragma unroll
        for (int kc = 0; kc < 8; kc++) {
            const int c = kc * 8 + a4;
            qf[kc][0] = f2tf32(qp[(size_t)r0 * HIDDEN + c] * sc);
            qf[kc][1] = f2tf32(qp[(size_t)(r0 + 8) * HIDDEN + c] * sc);
            qf[kc][2] = f2tf32(qp[(size_t)r0 * HIDDEN + c + 4] * sc);
            qf[kc][3] = f2tf32(qp[(size_t)(r0 + 8) * HIDDEN + c + 4] * sc);
        }
    }

    float o[8][4];
#pragma unroll
    for (int nt = 0; nt < 8; nt++) {
        o[nt][0] = 0.f; o[nt][1] = 0.f; o[nt][2] = 0.f; o[nt][3] = 0.f;
    }
    float mi0 = -1e30f, mi1 = -1e30f, l0s = 0.f, l1s = 0.f;

    const int ktEnd = 2 * qt + 1;

#pragma unroll
    for (int t = 0; t < 2; t++) {
        const uint32_t buf = sb + t * ASTG;
        const float* kp = ksrc + (size_t)t * 64 * KVW;
        const float* vp = vsrc + t * 64;
#pragma unroll
        for (int i = 0; i < 4; i++) {
            cp16(buf + dOff[i],        kp + i * 16);
            cp16(buf + KSTG + dOff[i], vp + i * 16);
        }
        CP_COMMIT();
    }

    int cur = 0;
    for (int kt = 0; kt <= ktEnd; kt++) {
        CP_WAIT1();
        __syncthreads();

        if (kt + 2 <= ktEnd) {
            int nb = cur + 2; if (nb >= 3) nb -= 3;
            const uint32_t buf = sb + nb * ASTG;
            const float* kp = ksrc + (size_t)(kt + 2) * 64 * KVW;
            const float* vp = vsrc + (kt + 2) * 64;
#pragma unroll
            for (int i = 0; i < 4; i++) {
                cp16(buf + dOff[i],        kp + i * 16);
                cp16(buf + KSTG + dOff[i], vp + i * 16);
            }
        }
        CP_COMMIT();

        const uint32_t kbuf = sb + cur * ASTG;
        const uint32_t vbuf = kbuf + KSTG;

        float s[8][4];
#pragma unroll
        for (int nt = 0; nt < 8; nt++) {
            s[nt][0] = 0.f; s[nt][1] = 0.f; s[nt][2] = 0.f; s[nt][3] = 0.f;
        }
#pragma unroll
        for (int kc = 0; kc < 8; kc++) {
            const uint32_t kk = ((((uint32_t)(kc << 1)) | cbit) ^ r7) << 4;
#pragma unroll
            for (int nt2 = 0; nt2 < 4; nt2++) {
                uint32_t bf[4];
                ldsm_x4(bf, kbuf + nt2 * 4096 + rterm + kk);
                mma_tf32(s[2 * nt2],     qf[kc], bf[0], bf[1]);
                mma_tf32(s[2 * nt2 + 1], qf[kc], bf[2], bf[3]);
            }
        }

        if (kt >= 2 * qt) {
            const int diff  = (kt - 2 * qt) * 64;
            const int row0g = w * 16 + r0, row1g = row0g + 8;
#pragma unroll
            for (int nt = 0; nt < 8; nt++) {
                const int c0 = nt * 8 + 2 * a4 + diff, c1 = c0 + 1;
                if (c0 > row0g) s[nt][0] = -1e30f;
                if (c1 > row0g) s[nt][1] = -1e30f;
                if (c0 > row1g) s[nt][2] = -1e30f;
                if (c1 > row1g) s[nt][3] = -1e30f;
            }
        }

        float mx0 = -1e30f, mx1 = -1e30f;
#pragma unroll
        for (int nt = 0; nt < 8; nt++) {
            mx0 = fmaxf(mx0, fmaxf(s[nt][0], s[nt][1]));
            mx1 = fmaxf(mx1, fmaxf(s[nt][2], s[nt][3]));
        }
        mx0 = fmaxf(mx0, __shfl_xor_sync(0xffffffffu, mx0, 1));
        mx0 = fmaxf(mx0, __shfl_xor_sync(0xffffffffu, mx0, 2));
        mx1 = fmaxf(mx1, __shfl_xor_sync(0xffffffffu, mx1, 1));
        mx1 = fmaxf(mx1, __shfl_xor_sync(0xffffffffu, mx1, 2));
        const float nm0 = fmaxf(mi0, mx0), nm1 = fmaxf(mi1, mx1);
        const float cr0 = __expf(mi0 - nm0), cr1 = __expf(mi1 - nm1);
        float sum0 = 0.f, sum1 = 0.f;
#pragma unroll
        for (int nt = 0; nt < 8; nt++) {
            s[nt][0] = __expf(s[nt][0] - nm0);
            s[nt][1] = __expf(s[nt][1] - nm0);
            s[nt][2] = __expf(s[nt][2] - nm1);
            s[nt][3] = __expf(s[nt][3] - nm1);
            sum0 += s[nt][0] + s[nt][1];
            sum1 += s[nt][2] + s[nt][3];
        }
        sum0 += __shfl_xor_sync(0xffffffffu, sum0, 1);
        sum0 += __shfl_xor_sync(0xffffffffu, sum0, 2);
        sum1 += __shfl_xor_sync(0xffffffffu, sum1, 1);
        sum1 += __shfl_xor_sync(0xffffffffu, sum1, 2);
        l0s = l0s * cr0 + sum0;  l1s = l1s * cr1 + sum1;
        mi0 = nm0;               mi1 = nm1;
#pragma unroll
        for (int nt = 0; nt < 8; nt++) {
            o[nt][0] *= cr0; o[nt][1] *= cr0;
            o[nt][2] *= cr1; o[nt][3] *= cr1;
        }

#pragma unroll
        for (int kc = 0; kc < 8; kc++) {
            uint32_t pa[4];
            {
                float v0 = __shfl_sync(0xffffffffu, s[kc][0], L0);
                float v1 = __shfl_sync(0xffffffffu, s[kc][1], L0);
                pa[0] = f2tf32(pOdd ? v1 : v0);
                float v2 = __shfl_sync(0xffffffffu, s[kc][2], L0);
                float v3 = __shfl_sync(0xffffffffu, s[kc][3], L0);
                pa[1] = f2tf32(pOdd ? v3 : v2);
                v0 = __shfl_sync(0xffffffffu, s[kc][0], L1);
                v1 = __shfl_sync(0xffffffffu, s[kc][1], L1);
                pa[2] = f2tf32(pOdd ? v1 : v0);
                v2 = __shfl_sync(0xffffffffu, s[kc][2], L1);
                v3 = __shfl_sync(0xffffffffu, s[kc][3], L1);
                pa[3] = f2tf32(pOdd ? v3 : v2);
            }
            const uint32_t kk = ((((uint32_t)(kc << 1)) | cbit) ^ r7) << 4;
#pragma unroll
            for (int nt2 = 0; nt2 < 4; nt2++) {
                uint32_t bf[4];
                ldsm_x4(bf, vbuf + nt2 * 4096 + rterm + kk);
                mma_tf32(o[2 * nt2],     pa, bf[0], bf[1]);
                mma_tf32(o[2 * nt2 + 1], pa, bf[2], bf[3]);
            }
        }

        cur++; if (cur == 3) cur = 0;
    }

    const float inv0 = 1.f / l0s, inv1 = 1.f / l1s;
    const size_t row0 = (size_t)(b * SEQ + qt * 128 + w * 16 + r0);
#pragma unroll
    for (int nt = 0; nt < 8; nt++) {
        const int col = h * HDIM + nt * 8 + 2 * a4;
        *(float2*)&Out[row0 * HIDDEN + col] = make_float2(
            __uint_as_float(f2tf32(o[nt][0] * inv0)),
            __uint_as_float(f2tf32(o[nt][1] * inv0)));
        *(float2*)&Out[(row0 + 8) * HIDDEN + col] = make_float2(
            __uint_as_float(f2tf32(o[nt][2] * inv1)),
            __uint_as_float(f2tf32(o[nt][3] * inv1)));
    }
}

/* ================================================================= */
extern "C" void kernel_launch(void* const* d_in, const int* in_sizes, int n_in,
                              void* d_out, int out_size)
{
    (void)in_sizes; (void)n_in; (void)out_size;
    const float* x  = (const float*)d_in[0];
    /* d_in[1] = causal mask, handled analytically */
    const float* Wq = (const float*)d_in[2];
    const float* bq = (const float*)d_in[3];
    const float* Wk = (const float*)d_in[4];
    const float* bk = (const float*)d_in[5];
    const float* Wv = (const float*)d_in[6];
    const float* bv = (const float*)d_in[7];
    const float* Wo = (const float*)d_in[8];
    const float* bo = (const float*)d_in[9];
    float* out = (float*)d_out;

    float *q, *k, *vt, *attn;
    cudaGetSymbolAddress((void**)&q,    g_q);
    cudaGetSymbolAddress((void**)&k,    g_k);
    cudaGetSymbolAddress((void**)&vt,   g_vt);
    cudaGetSymbolAddress((void**)&attn, g_attn);

    cudaFuncSetAttribute(qkv_gemm,   cudaFuncAttributeMaxDynamicSharedMemorySize, GEMM_SMEM);
    cudaFuncSetAttribute(oproj_gemm, cudaFuncAttributeMaxDynamicSharedMemorySize, GEMM_SMEM);
    cudaFuncSetAttribute(attn_tc,    cudaFuncAttributeMaxDynamicSharedMemorySize, ATT_SMEM);

    /* 1. fused Q/K/V projection (in-register tf32 cvt; K tf32,
          V tf32-transposed epilogues) */
    qkv_gemm<<<dim3(24, 16), 128, GEMM_SMEM>>>(x, Wq, bq, Wk, bk, Wv, bv);

    /* 2. causal GQA attention */
    attn_tc<<<dim3(SEQ / 128, NHEADS, BATCH), 256, ATT_SMEM>>>(q, k, vt, attn);

    /* 3. output projection */
    oproj_gemm<<<dim3(16, 16), 128, GEMM_SMEM>>>(Wo, bo, out);
}

// round 13
// speedup vs baseline: 1.6174x; 1.0151x over previous
#include <cuda_runtime.h>
#include <math.h>
#include <stdint.h>

#define HIDDEN 2048
#define SEQ    1024
#define BATCH  2
#define NHEADS 32
#define NGROUP 8
#define HDIM   64
#define MTOT   (BATCH * SEQ)
#define KVW    (NGROUP * HDIM)    /* 512  */

/* ---------------- scratch (no cudaMalloc allowed) ---------------- */
__device__ float g_q  [MTOT * HIDDEN];               /* fp32           */
__device__ float g_k  [MTOT * KVW];                  /* tf32 bits      */
__device__ float g_vt [BATCH * NGROUP * HDIM * SEQ]; /* tf32, [b,g,d,s]*/
__device__ float g_attn[MTOT * HIDDEN];              /* tf32 bits      */

/* ---------------- helpers ---------------- */
__device__ __forceinline__ uint32_t f2tf32(float x) {
    uint32_t r;
    asm("cvt.rna.tf32.f32 %0, %1;" : "=r"(r) : "f"(x));
    return r;
}
__device__ __forceinline__ uint32_t u2tf32(uint32_t x) {
    uint32_t r;
    asm("cvt.rna.tf32.f32 %0, %1;" : "=r"(r) : "f"(__uint_as_float(x)));
    return r;
}
__device__ __forceinline__ uint32_t smem_u32(const void* p) {
    uint32_t a;
    asm("{ .reg .u64 t; cvta.to.shared.u64 t, %1; cvt.u32.u64 %0, t; }"
        : "=r"(a) : "l"(p));
    return a;
}
__device__ __forceinline__ void mma_tf32(float* c, const uint32_t* a,
                                         uint32_t b0, uint32_t b1) {
    asm volatile(
        "mma.sync.aligned.m16n8k8.row.col.f32.tf32.tf32.f32 "
        "{%0,%1,%2,%3}, {%4,%5,%6,%7}, {%8,%9}, {%0,%1,%2,%3};"
        : "+f"(c[0]), "+f"(c[1]), "+f"(c[2]), "+f"(c[3])
        : "r"(a[0]), "r"(a[1]), "r"(a[2]), "r"(a[3]), "r"(b0), "r"(b1));
}
__device__ __forceinline__ void ldsm_x4(uint32_t* r, uint32_t addr) {
    asm volatile("ldmatrix.sync.aligned.m8n8.x4.shared.b16 {%0,%1,%2,%3}, [%4];"
        : "=r"(r[0]), "=r"(r[1]), "=r"(r[2]), "=r"(r[3]) : "r"(addr));
}
__device__ __forceinline__ void cp16(uint32_t dst, const void* src) {
    asm volatile("cp.async.cg.shared.global [%0], [%1], 16;"
                 :: "r"(dst), "l"(src));
}
#define CP_COMMIT() asm volatile("cp.async.commit_group;" ::: "memory")
#define CP_WAIT0()  asm volatile("cp.async.wait_group 0;"  ::: "memory")
#define CP_WAIT1()  asm volatile("cp.async.wait_group 1;"  ::: "memory")

/* =================================================================
 * TF32 NT GEMM core: CTA 128x128, 128 threads (4 warps 2x2),
 * warp tile 64x64, BK=32, 3-stage cp.async (wait_group 1),
 * XOR-swizzled 128B rows. 96KB smem -> 2 CTAs/SM, 255-reg budget
 * (launch_bounds(128,2)) so ptxas software-pipelines LDSM/CVT.
 * CVTA: convert A fragments to tf32 (false when A already tf32).
 * MODE: 0 fp32+bias | 1 tf32+bias | 2 tf32+bias transposed to g_vt.
 * ================================================================= */
#define BK    32
#define TILEB 16384
#define STAGE (2 * TILEB)              /* 32768 */
#define NST   3
#define GEMM_SMEM (NST * STAGE)        /* 98304 */

template<int MODE, bool CVTA>
__device__ __forceinline__ void gemm_core(
    const float* __restrict__ A, const float* __restrict__ Bm,
    const float* __restrict__ bias, float* __restrict__ C,
    int ldc, int K, int m0, int n0B, int n0C)
{
    extern __shared__ char smem[];
    const uint32_t sb = smem_u32(smem);
    const int tid = threadIdx.x, lane = tid & 31, wid = tid >> 5;
    const int wm = (wid & 1) * 64, wn = (wid >> 1) * 64;
    const int grp = lane >> 3;

    const uint32_t xm   = (uint32_t)(lane & 7) << 4;
    const uint32_t rowA = (uint32_t)(wm + (lane & 7) + ((grp & 1) << 3)) * 128;
    const uint32_t rowB = (uint32_t)(wn + (lane & 7) + ((grp >> 1) << 3)) * 128;
    const uint32_t cA   = (uint32_t)(grp >> 1) << 4;
    const uint32_t cB   = (uint32_t)(grp & 1) << 4;

    float acc[4][8][4];
#pragma unroll
    for (int mt = 0; mt < 4; mt++)
#pragma unroll
        for (int nt = 0; nt < 8; nt++) {
            acc[mt][nt][0] = 0.f; acc[mt][nt][1] = 0.f;
            acc[mt][nt][2] = 0.f; acc[mt][nt][3] = 0.f;
        }

    const float* Ag = A  + (size_t)(m0  + tid) * K;
    const float* Bg = Bm + (size_t)(n0B + tid) * K;
    const uint32_t sRow = (uint32_t)tid * 128;
    const uint32_t sX   = (uint32_t)(tid & 7) << 4;
    const int nIter = K / BK;

    /* prologue: stages 0 and 1, separate commit groups */
#pragma unroll
    for (int s = 0; s < NST - 1; s++) {
        const uint32_t buf = sb + s * STAGE;
#pragma unroll
        for (int i = 0; i < 8; i++) {
            const uint32_t d = sRow + (((uint32_t)i << 4) ^ sX);
            cp16(buf + d,         Ag + s * BK + i * 4);
            cp16(buf + TILEB + d, Bg + s * BK + i * 4);
        }
        CP_COMMIT();
    }

    int cur = 0;
    for (int it = 0; it < nIter; it++) {
        CP_WAIT1();            /* stage it ready; it+1 may be in flight */
        __syncthreads();       /* everyone done reading stage it-1     */

        int pfb = cur + 2; if (pfb >= NST) pfb -= NST;
        const uint32_t nx = sb + pfb * STAGE;
        const bool pf = (it + 2 < nIter);
        const float* Ap = Ag + (it + 2) * BK;
        const float* Bp = Bg + (it + 2) * BK;

        const uint32_t aB = sb + cur * STAGE;
        const uint32_t bB = aB + TILEB;

#pragma unroll
        for (int ks = 0; ks < 4; ks++) {
            if (pf) {
                const uint32_t d0 = sRow + ((((uint32_t)(2 * ks) << 4))     ^ sX);
                const uint32_t d1 = sRow + ((((uint32_t)(2 * ks + 1) << 4)) ^ sX);
                cp16(nx + d0,         Ap + (2 * ks) * 4);
                cp16(nx + d1,         Ap + (2 * ks + 1) * 4);
                cp16(nx + TILEB + d0, Bp + (2 * ks) * 4);
                cp16(nx + TILEB + d1, Bp + (2 * ks + 1) * 4);
            }
            const uint32_t ck = ((uint32_t)ks << 5);
            uint32_t af[4][4];
#pragma unroll
            for (int mt = 0; mt < 4; mt++) {
                ldsm_x4(af[mt], aB + rowA + mt * 2048 + ((ck + cA) ^ xm));
                if (CVTA) {
                    af[mt][0] = u2tf32(af[mt][0]); af[mt][1] = u2tf32(af[mt][1]);
                    af[mt][2] = u2tf32(af[mt][2]); af[mt][3] = u2tf32(af[mt][3]);
                }
            }
            uint32_t bf[2][4];
            ldsm_x4(bf[0], bB + rowB + ((ck + cB) ^ xm));
            bf[0][0] = u2tf32(bf[0][0]); bf[0][1] = u2tf32(bf[0][1]);
            bf[0][2] = u2tf32(bf[0][2]); bf[0][3] = u2tf32(bf[0][3]);
#pragma unroll
            for (int nt2 = 0; nt2 < 4; nt2++) {
                const int c = nt2 & 1, n = 1 - c;
                if (nt2 < 3) {
                    ldsm_x4(bf[n], bB + rowB + (nt2 + 1) * 2048 + ((ck + cB) ^ xm));
                    bf[n][0] = u2tf32(bf[n][0]); bf[n][1] = u2tf32(bf[n][1]);
                    bf[n][2] = u2tf32(bf[n][2]); bf[n][3] = u2tf32(bf[n][3]);
                }
#pragma unroll
                for (int mt = 0; mt < 4; mt++) {
                    mma_tf32(acc[mt][2 * nt2],     af[mt], bf[c][0], bf[c][1]);
                    mma_tf32(acc[mt][2 * nt2 + 1], af[mt], bf[c][2], bf[c][3]);
                }
            }
        }
        CP_COMMIT();
        cur++; if (cur == NST) cur = 0;
    }

    const int r0 = lane >> 2, a4 = lane & 3;
#pragma unroll
    for (int mt = 0; mt < 4; mt++) {
#pragma unroll
        for (int nt = 0; nt < 8; nt++) {
            const int col = n0C + wn + nt * 8 + 2 * a4;
            const float b0 = bias[col], b1 = bias[col + 1];
            const int rA = m0 + wm + mt * 16 + r0;
            if (MODE == 0) {
                *(float2*)&C[(size_t)rA * ldc + col] =
                    make_float2(acc[mt][nt][0] + b0, acc[mt][nt][1] + b1);
                *(float2*)&C[(size_t)(rA + 8) * ldc + col] =
                    make_float2(acc[mt][nt][2] + b0, acc[mt][nt][3] + b1);
            } else if (MODE == 1) {
                *(float2*)&C[(size_t)rA * ldc + col] = make_float2(
                    __uint_as_float(f2tf32(acc[mt][nt][0] + b0)),
                    __uint_as_float(f2tf32(acc[mt][nt][1] + b1)));
                *(float2*)&C[(size_t)(rA + 8) * ldc + col] = make_float2(
                    __uint_as_float(f2tf32(acc[mt][nt][2] + b0)),
                    __uint_as_float(f2tf32(acc[mt][nt][3] + b1)));
            } else {
                /* transposed tf32 store into g_vt[b,g,d,s] */
                const int r1 = rA + 8;
#pragma unroll
                for (int q = 0; q < 2; q++) {
                    const int r = q ? r1 : rA;
                    const size_t base =
                        ((size_t)((r >> 10) * 8 + (col >> 6)) * 64) * 1024
                        + (size_t)(r & 1023);
                    g_vt[base + (size_t)(col & 63) * 1024] =
                        __uint_as_float(f2tf32(acc[mt][nt][2 * q] + b0));
                    g_vt[base + (size_t)((col & 63) + 1) * 1024] =
                        __uint_as_float(f2tf32(acc[mt][nt][2 * q + 1] + b1));
                }
            }
        }
    }
}

/* fused QKV projection: grid (24, 16) */
__global__ __launch_bounds__(128, 2) void qkv_gemm(
    const float* __restrict__ x,
    const float* __restrict__ Wq, const float* __restrict__ bq,
    const float* __restrict__ Wk, const float* __restrict__ bk,
    const float* __restrict__ Wv, const float* __restrict__ bv)
{
    const int n0 = blockIdx.x * 128, m0 = blockIdx.y * 128;
    if (n0 < 2048)
        gemm_core<0, true>(x, Wq, bq, g_q, HIDDEN, HIDDEN, m0, n0, n0);
    else if (n0 < 2560)
        gemm_core<1, true>(x, Wk, bk, g_k, KVW, HIDDEN, m0, n0 - 2048, n0 - 2048);
    else
        gemm_core<2, true>(x, Wv, bv, (float*)0, KVW, HIDDEN, m0, n0 - 2560, n0 - 2560);
}

/* O projection: grid (16, 16); A (g_attn) is already tf32 bits */
__global__ __launch_bounds__(128, 2) void oproj_gemm(
    const float* __restrict__ Wo, const float* __restrict__ bo,
    float* __restrict__ out)
{
    gemm_core<0, false>(g_attn, Wo, bo, out, HIDDEN, HIDDEN,
                        blockIdx.y * 128, blockIdx.x * 128, blockIdx.x * 128);
}

/* =================================================================
 * Flash attention (causal, GQA): 128 q-rows/CTA, 256 thr, 8 warps.
 * K/V staged via cp.async (V pre-transposed tf32); P in registers
 * via lane-shuffle C-frag -> A-frag conversion. 1 barrier per tile.
 * ================================================================= */
#define KSTG  16384                    /* 64 rows x 256 B */
#define ASTG  (2 * KSTG)
#define ATT_SMEM (3 * ASTG)            /* 98304 */

__global__ __launch_bounds__(256, 2) void attn_tc(
    const float* __restrict__ Q, const float* __restrict__ Kp,
    const float* __restrict__ Vtg, float* __restrict__ Out)
{
    extern __shared__ char smA[];
    const uint32_t sb = smem_u32(smA);

    const int qt = (int)gridDim.x - 1 - (int)blockIdx.x;  /* longest first */
    const int h = blockIdx.y, b = blockIdx.z, g = h >> 2;
    const int tid = threadIdx.x, lane = tid & 31, w = tid >> 5;
    const int r0 = lane >> 2, a4 = lane & 3;
    const int grp = lane >> 3;

    const int srow = tid >> 2, csel = tid & 3;
    const float* ksrc = Kp  + ((size_t)(b * SEQ) + srow) * KVW + g * HDIM + csel * 4;
    const float* vsrc = Vtg + ((size_t)((b * NGROUP + g) * HDIM + srow)) * SEQ + csel * 4;
    uint32_t dOff[4];
#pragma unroll
    for (int i = 0; i < 4; i++)
        dOff[i] = (uint32_t)srow * 256 + ((uint32_t)((4 * i + csel) ^ (srow & 7)) << 4);

    const uint32_t rown  = (uint32_t)((lane & 7) + ((grp >> 1) << 3));
    const uint32_t rterm = rown * 256;
    const uint32_t r7    = rown & 7;
    const uint32_t cbit  = (uint32_t)(grp & 1);

    const int L0 = r0 * 4 + (a4 >> 1), L1 = L0 + 2;
    const bool pOdd = (a4 & 1) != 0;

    uint32_t qf[8][4];
    {
        const float sc = 0.125f;
        const float* qp = Q + (size_t)(b * SEQ + qt * 128 + w * 16) * HIDDEN + h * HDIM;
#pragma unroll
        for (int kc = 0; kc < 8; kc++) {
            const int c = kc * 8 + a4;
            qf[kc][0] = f2tf32(qp[(size_t)r0 * HIDDEN + c] * sc);
            qf[kc][1] = f2tf32(qp[(size_t)(r0 + 8) * HIDDEN + c] * sc);
            qf[kc][2] = f2tf32(qp[(size_t)r0 * HIDDEN + c + 4] * sc);
            qf[kc][3] = f2tf32(qp[(size_t)(r0 + 8) * HIDDEN + c + 4] * sc);
        }
    }

    float o[8][4];
#pragma unroll
    for (int nt = 0; nt < 8; nt++) {
        o[nt][0] = 0.f; o[nt][1] = 0.f; o[nt][2] = 0.f; o[nt][3] = 0.f;
    }
    float mi0 = -1e30f, mi1 = -1e30f, l0s = 0.f, l1s = 0.f;

    const int ktEnd = 2 * qt + 1;

#pragma unroll
    for (int t = 0; t < 2; t++) {
        const uint32_t buf = sb + t * ASTG;
        const float* kp = ksrc + (size_t)t * 64 * KVW;
        const float* vp = vsrc + t * 64;
#pragma unroll
        for (int i = 0; i < 4; i++) {
            cp16(buf + dOff[i],        kp + i * 16);
            cp16(buf + KSTG + dOff[i], vp + i * 16);
        }
        CP_COMMIT();
    }

    int cur = 0;
    for (int kt = 0; kt <= ktEnd; kt++) {
        CP_WAIT1();
        __syncthreads();

        if (kt + 2 <= ktEnd) {
            int nb = cur + 2; if (nb >= 3) nb -= 3;
            const uint32_t buf = sb + nb * ASTG;
            const float* kp = ksrc + (size_t)(kt + 2) * 64 * KVW;
            const float* vp = vsrc + (kt + 2) * 64;
#pragma unroll
            for (int i = 0; i < 4; i++) {
                cp16(buf + dOff[i],        kp + i * 16);
                cp16(buf + KSTG + dOff[i], vp + i * 16);
            }
        }
        CP_COMMIT();

        const uint32_t kbuf = sb + cur * ASTG;
        const uint32_t vbuf = kbuf + KSTG;

        float s[8][4];
#pragma unroll
        for (int nt = 0; nt < 8; nt++) {
            s[nt][0] = 0.f; s[nt][1] = 0.f; s[nt][2] = 0.f; s[nt][3] = 0.f;
        }
#pragma unroll
        for (int kc = 0; kc < 8; kc++) {
            const uint32_t kk = ((((uint32_t)(kc << 1)) | cbit) ^ r7) << 4;
#pragma unroll
            for (int nt2 = 0; nt2 < 4; nt2++) {
                uint32_t bf[4];
                ldsm_x4(bf, kbuf + nt2 * 4096 + rterm + kk);
                mma_tf32(s[2 * nt2],     qf[kc], bf[0], bf[1]);
                mma_tf32(s[2 * nt2 + 1], qf[kc], bf[2], bf[3]);
            }
        }

        if (kt >= 2 * qt) {
            const int diff  = (kt - 2 * qt) * 64;
            const int row0g = w * 16 + r0, row1g = row0g + 8;
#pragma unroll
            for (int nt = 0; nt < 8; nt++) {
                const int c0 = nt * 8 + 2 * a4 + diff, c1 = c0 + 1;
                if (c0 > row0g) s[nt][0] = -1e30f;
                if (c1 > row0g) s[nt][1] = -1e30f;
                if (c0 > row1g) s[nt][2] = -1e30f;
                if (c1 > row1g) s[nt][3] = -1e30f;
            }
        }

        float mx0 = -1e30f, mx1 = -1e30f;
#pragma unroll
        for (int nt = 0; nt < 8; nt++) {
            mx0 = fmaxf(mx0, fmaxf(s[nt][0], s[nt][1]));
            mx1 = fmaxf(mx1, fmaxf(s[nt][2], s[nt][3]));
        }
        mx0 = fmaxf(mx0, __shfl_xor_sync(0xffffffffu, mx0, 1));
        mx0 = fmaxf(mx0, __shfl_xor_sync(0xffffffffu, mx0, 2));
        mx1 = fmaxf(mx1, __shfl_xor_sync(0xffffffffu, mx1, 1));
        mx1 = fmaxf(mx1, __shfl_xor_sync(0xffffffffu, mx1, 2));
        const float nm0 = fmaxf(mi0, mx0), nm1 = fmaxf(mi1, mx1);
        const float cr0 = __expf(mi0 - nm0), cr1 = __expf(mi1 - nm1);
        float sum0 = 0.f, sum1 = 0.f;
#pragma unroll
        for (int nt = 0; nt < 8; nt++) {
            s[nt][0] = __expf(s[nt][0] - nm0);
            s[nt][1] = __expf(s[nt][1] - nm0);
            s[nt][2] = __expf(s[nt][2] - nm1);
            s[nt][3] = __expf(s[nt][3] - nm1);
            sum0 += s[nt][0] + s[nt][1];
            sum1 += s[nt][2] + s[nt][3];
        }
        sum0 += __shfl_xor_sync(0xffffffffu, sum0, 1);
        sum0 += __shfl_xor_sync(0xffffffffu, sum0, 2);
        sum1 += __shfl_xor_sync(0xffffffffu, sum1, 1);
        sum1 += __shfl_xor_sync(0xffffffffu, sum1, 2);
        l0s = l0s * cr0 + sum0;  l1s = l1s * cr1 + sum1;
        mi0 = nm0;               mi1 = nm1;
#pragma unroll
        for (int nt = 0; nt < 8; nt++) {
            o[nt][0] *= cr0; o[nt][1] *= cr0;
            o[nt][2] *= cr1; o[nt][3] *= cr1;
        }

#pragma unroll
        for (int kc = 0; kc < 8; kc++) {
            uint32_t pa[4];
            {
                float v0 = __shfl_sync(0xffffffffu, s[kc][0], L0);
                float v1 = __shfl_sync(0xffffffffu, s[kc][1], L0);
                pa[0] = f2tf32(pOdd ? v1 : v0);
                float v2 = __shfl_sync(0xffffffffu, s[kc][2], L0);
                float v3 = __shfl_sync(0xffffffffu, s[kc][3], L0);
                pa[1] = f2tf32(pOdd ? v3 : v2);
                v0 = __shfl_sync(0xffffffffu, s[kc][0], L1);
                v1 = __shfl_sync(0xffffffffu, s[kc][1], L1);
                pa[2] = f2tf32(pOdd ? v1 : v0);
                v2 = __shfl_sync(0xffffffffu, s[kc][2], L1);
                v3 = __shfl_sync(0xffffffffu, s[kc][3], L1);
                pa[3] = f2tf32(pOdd ? v3 : v2);
            }
            const uint32_t kk = ((((uint32_t)(kc << 1)) | cbit) ^ r7) << 4;
#pragma unroll
            for (int nt2 = 0; nt2 < 4; nt2++) {
                uint32_t bf[4];
                ldsm_x4(bf, vbuf + nt2 * 4096 + rterm + kk);
                mma_tf32(o[2 * nt2],     pa, bf[0], bf[1]);
                mma_tf32(o[2 * nt2 + 1], pa, bf[2], bf[3]);
            }
        }

        cur++; if (cur == 3) cur = 0;
    }

    const float inv0 = 1.f / l0s, inv1 = 1.f / l1s;
    const size_t row0 = (size_t)(b * SEQ + qt * 128 + w * 16 + r0);
#pragma unroll
    for (int nt = 0; nt < 8; nt++) {
        const int col = h * HDIM + nt * 8 + 2 * a4;
        *(float2*)&Out[row0 * HIDDEN + col] = make_float2(
            __uint_as_float(f2tf32(o[nt][0] * inv0)),
            __uint_as_float(f2tf32(o[nt][1] * inv0)));
        *(float2*)&Out[(row0 + 8) * HIDDEN + col] = make_float2(
            __uint_as_float(f2tf32(o[nt][2] * inv1)),
            __uint_as_float(f2tf32(o[nt][3] * inv1)));
    }
}

/* ================================================================= */
extern "C" void kernel_launch(void* const* d_in, const int* in_sizes, int n_in,
                              void* d_out, int out_size)
{
    (void)in_sizes; (void)n_in; (void)out_size;
    const float* x  = (const float*)d_in[0];
    /* d_in[1] = causal mask, handled analytically */
    const float* Wq = (const float*)d_in[2];
    const float* bq = (const float*)d_in[3];
    const float* Wk = (const float*)d_in[4];
    const float* bk = (const float*)d_in[5];
    const float* Wv = (const float*)d_in[6];
    const float* bv = (const float*)d_in[7];
    const float* Wo = (const float*)d_in[8];
    const float* bo = (const float*)d_in[9];
    float* out = (float*)d_out;

    float *q, *k, *vt, *attn;
    cudaGetSymbolAddress((void**)&q,    g_q);
    cudaGetSymbolAddress((void**)&k,    g_k);
    cudaGetSymbolAddress((void**)&vt,   g_vt);
    cudaGetSymbolAddress((void**)&attn, g_attn);

    cudaFuncSetAttribute(qkv_gemm,   cudaFuncAttributeMaxDynamicSharedMemorySize, GEMM_SMEM);
    cudaFuncSetAttribute(oproj_gemm, cudaFuncAttributeMaxDynamicSharedMemorySize, GEMM_SMEM);
    cudaFuncSetAttribute(attn_tc,    cudaFuncAttributeMaxDynamicSharedMemorySize, ATT_SMEM);

    /* 1. fused Q/K/V projection */
    qkv_gemm<<<dim3(24, 16), 128, GEMM_SMEM>>>(x, Wq, bq, Wk, bk, Wv, bv);

    /* 2. causal GQA attention */
    attn_tc<<<dim3(SEQ / 128, NHEADS, BATCH), 256, ATT_SMEM>>>(q, k, vt, attn);

    /* 3. output projection */
    oproj_gemm<<<dim3(16, 16), 128, GEMM_SMEM>>>(Wo, bo, out);
}

// round 14
// speedup vs baseline: 2.9009x; 1.7936x over previous
#include <cuda_runtime.h>
#include <cuda_fp16.h>
#include <math.h>
#include <stdint.h>

#define HIDDEN 2048
#define SEQ    1024
#define BATCH  2
#define NHEADS 32
#define NGROUP 8
#define HDIM   64
#define MTOT   (BATCH * SEQ)
#define KVW    (NGROUP * HDIM)    /* 512  */
#define QKVW   (HIDDEN + 2 * KVW) /* 3072 */

/* ---------------- scratch (no cudaMalloc allowed) ---------------- */
__device__ __align__(16) __half g_xh  [MTOT * HIDDEN];
__device__ __align__(16) __half g_wh  [QKVW * HIDDEN];   /* Wq|Wk|Wv */
__device__ __align__(16) __half g_woh [HIDDEN * HIDDEN];
__device__ float                g_q   [MTOT * HIDDEN];   /* fp32 Q   */
__device__ __align__(16) __half g_kh  [MTOT * KVW];
__device__ __align__(16) __half g_vth [BATCH * NGROUP * HDIM * SEQ]; /* [b,g,d,s] */
__device__ __align__(16) __half g_attnh[MTOT * HIDDEN];

/* ---------------- helpers ---------------- */
__device__ __forceinline__ uint32_t pack_h2(float lo, float hi) {
    __half2 h = __floats2half2_rn(lo, hi);
    return *reinterpret_cast<uint32_t*>(&h);
}
__device__ __forceinline__ uint32_t smem_u32(const void* p) {
    uint32_t a;
    asm("{ .reg .u64 t; cvta.to.shared.u64 t, %1; cvt.u32.u64 %0, t; }"
        : "=r"(a) : "l"(p));
    return a;
}
__device__ __forceinline__ void mma_f16(float* c, const uint32_t* a,
                                        uint32_t b0, uint32_t b1) {
    asm volatile(
        "mma.sync.aligned.m16n8k16.row.col.f32.f16.f16.f32 "
        "{%0,%1,%2,%3}, {%4,%5,%6,%7}, {%8,%9}, {%0,%1,%2,%3};"
        : "+f"(c[0]), "+f"(c[1]), "+f"(c[2]), "+f"(c[3])
        : "r"(a[0]), "r"(a[1]), "r"(a[2]), "r"(a[3]), "r"(b0), "r"(b1));
}
__device__ __forceinline__ void ldsm_x4(uint32_t* r, uint32_t addr) {
    asm volatile("ldmatrix.sync.aligned.m8n8.x4.shared.b16 {%0,%1,%2,%3}, [%4];"
        : "=r"(r[0]), "=r"(r[1]), "=r"(r[2]), "=r"(r[3]) : "r"(addr));
}
__device__ __forceinline__ void cp16(uint32_t dst, const void* src) {
    asm volatile("cp.async.cg.shared.global [%0], [%1], 16;"
                 :: "r"(dst), "l"(src));
}
#define CP_COMMIT() asm volatile("cp.async.commit_group;" ::: "memory")
#define CP_WAIT1()  asm volatile("cp.async.wait_group 1;"  ::: "memory")

/* =================================================================
 * Pre-convert x, Wq|Wk|Wv, Wo to fp16 (grid-stride, float4 -> uint2).
 * ================================================================= */
__global__ void cvt_all(const float4* __restrict__ x,
                        const float4* __restrict__ wq,
                        const float4* __restrict__ wk,
                        const float4* __restrict__ wv,
                        const float4* __restrict__ wo)
{
    const int64_t N0 = 1048576;          /* x  float4s */
    const int64_t N1 = N0 + 1048576;     /* Wq */
    const int64_t N2 = N1 + 262144;      /* Wk */
    const int64_t N3 = N2 + 262144;      /* Wv */
    const int64_t N4 = N3 + 1048576;     /* Wo */
    uint2* xh = (uint2*)g_xh;
    uint2* wh = (uint2*)g_wh;
    uint2* wo2 = (uint2*)g_woh;
    for (int64_t i = (int64_t)blockIdx.x * blockDim.x + threadIdx.x;
         i < N4; i += (int64_t)gridDim.x * blockDim.x) {
        float4 v; uint2* dst;
        if (i < N0)      { v = x [i];      dst = xh + i; }
        else if (i < N1) { v = wq[i - N0]; dst = wh + (i - N0); }
        else if (i < N2) { v = wk[i - N1]; dst = wh + 1048576 + (i - N1); }
        else if (i < N3) { v = wv[i - N2]; dst = wh + 1310720 + (i - N2); }
        else             { v = wo[i - N3]; dst = wo2 + (i - N3); }
        uint2 u;
        u.x = pack_h2(v.x, v.y);
        u.y = pack_h2(v.z, v.w);
        *dst = u;
    }
}

/* =================================================================
 * FP16 NT GEMM core: CTA 128x128, 128 threads (4 warps 2x2),
 * warp tile 64x64, BK=64 halves (128B rows), 3-stage cp.async
 * (wait_group 1), XOR-swizzled. 96KB smem -> 2 CTAs/SM.
 * MODE: 0 fp32+bias | 1 fp16+bias (K) | 2 fp16+bias transposed (Vt).
 * ================================================================= */
#define BK    64                       /* halves per chunk */
#define TILEB 16384                    /* 128 rows x 128B  */
#define STAGE (2 * TILEB)
#define NST   3
#define GEMM_SMEM (NST * STAGE)        /* 98304 */

template<int MODE>
__device__ __forceinline__ void gemm_core(
    const __half* __restrict__ A, const __half* __restrict__ Bm,
    const float* __restrict__ bias, float* __restrict__ C,
    __half* __restrict__ Ch, int ldc, int K, int m0, int n0B, int n0C)
{
    extern __shared__ char smem[];
    const uint32_t sb = smem_u32(smem);
    const int tid = threadIdx.x, lane = tid & 31, wid = tid >> 5;
    const int wm = (wid & 1) * 64, wn = (wid >> 1) * 64;
    const int grp = lane >> 3;

    const uint32_t xm   = (uint32_t)(lane & 7) << 4;
    const uint32_t rowA = (uint32_t)(wm + (lane & 7) + ((grp & 1) << 3)) * 128;
    const uint32_t rowB = (uint32_t)(wn + (lane & 7) + ((grp >> 1) << 3)) * 128;
    const uint32_t cA   = (uint32_t)(grp >> 1) << 4;
    const uint32_t cB   = (uint32_t)(grp & 1) << 4;

    float acc[4][8][4];
#pragma unroll
    for (int mt = 0; mt < 4; mt++)
#pragma unroll
        for (int nt = 0; nt < 8; nt++) {
            acc[mt][nt][0] = 0.f; acc[mt][nt][1] = 0.f;
            acc[mt][nt][2] = 0.f; acc[mt][nt][3] = 0.f;
        }

    const __half* Ag = A  + (size_t)(m0  + tid) * K;
    const __half* Bg = Bm + (size_t)(n0B + tid) * K;
    const uint32_t sRow = (uint32_t)tid * 128;
    const uint32_t sX   = (uint32_t)(tid & 7) << 4;
    const int nIter = K / BK;

    /* prologue: stages 0 and 1 */
#pragma unroll
    for (int s = 0; s < NST - 1; s++) {
        const uint32_t buf = sb + s * STAGE;
#pragma unroll
        for (int i = 0; i < 8; i++) {
            const uint32_t d = sRow + (((uint32_t)i << 4) ^ sX);
            cp16(buf + d,         Ag + s * BK + i * 8);
            cp16(buf + TILEB + d, Bg + s * BK + i * 8);
        }
        CP_COMMIT();
    }

    int cur = 0;
    for (int it = 0; it < nIter; it++) {
        CP_WAIT1();
        __syncthreads();

        int pfb = cur + 2; if (pfb >= NST) pfb -= NST;
        const uint32_t nx = sb + pfb * STAGE;
        const bool pf = (it + 2 < nIter);
        const __half* Ap = Ag + (it + 2) * BK;
        const __half* Bp = Bg + (it + 2) * BK;

        const uint32_t aB = sb + cur * STAGE;
        const uint32_t bB = aB + TILEB;

#pragma unroll
        for (int ks = 0; ks < 4; ks++) {           /* k16 steps */
            if (pf) {
                const uint32_t d0 = sRow + ((((uint32_t)(2 * ks) << 4))     ^ sX);
                const uint32_t d1 = sRow + ((((uint32_t)(2 * ks + 1) << 4)) ^ sX);
                cp16(nx + d0,         Ap + (2 * ks) * 8);
                cp16(nx + d1,         Ap + (2 * ks + 1) * 8);
                cp16(nx + TILEB + d0, Bp + (2 * ks) * 8);
                cp16(nx + TILEB + d1, Bp + (2 * ks + 1) * 8);
            }
            const uint32_t ck = ((uint32_t)ks << 5);   /* 32B per k16 */
            uint32_t af[4][4];
#pragma unroll
            for (int mt = 0; mt < 4; mt++)
                ldsm_x4(af[mt], aB + rowA + mt * 2048 + ((ck + cA) ^ xm));
            uint32_t bf[2][4];
            ldsm_x4(bf[0], bB + rowB + ((ck + cB) ^ xm));
#pragma unroll
            for (int nt2 = 0; nt2 < 4; nt2++) {        /* n16 groups */
                const int c = nt2 & 1, n = 1 - c;
                if (nt2 < 3)
                    ldsm_x4(bf[n], bB + rowB + (nt2 + 1) * 2048 + ((ck + cB) ^ xm));
#pragma unroll
                for (int mt = 0; mt < 4; mt++) {
                    mma_f16(acc[mt][2 * nt2],     af[mt], bf[c][0], bf[c][1]);
                    mma_f16(acc[mt][2 * nt2 + 1], af[mt], bf[c][2], bf[c][3]);
                }
            }
        }
        CP_COMMIT();
        cur++; if (cur == NST) cur = 0;
    }

    const int r0 = lane >> 2, a4 = lane & 3;
#pragma unroll
    for (int mt = 0; mt < 4; mt++) {
#pragma unroll
        for (int nt = 0; nt < 8; nt++) {
            const int col = n0C + wn + nt * 8 + 2 * a4;
            const float b0 = bias[col], b1 = bias[col + 1];
            const int rA = m0 + wm + mt * 16 + r0;
            if (MODE == 0) {
                *(float2*)&C[(size_t)rA * ldc + col] =
                    make_float2(acc[mt][nt][0] + b0, acc[mt][nt][1] + b1);
                *(float2*)&C[(size_t)(rA + 8) * ldc + col] =
                    make_float2(acc[mt][nt][2] + b0, acc[mt][nt][3] + b1);
            } else if (MODE == 1) {
                *(uint32_t*)&Ch[(size_t)rA * ldc + col] =
                    pack_h2(acc[mt][nt][0] + b0, acc[mt][nt][1] + b1);
                *(uint32_t*)&Ch[(size_t)(rA + 8) * ldc + col] =
                    pack_h2(acc[mt][nt][2] + b0, acc[mt][nt][3] + b1);
            } else {
                /* transposed fp16 store into g_vth[b,g,d,s] */
                const int r1 = rA + 8;
#pragma unroll
                for (int q = 0; q < 2; q++) {
                    const int r = q ? r1 : rA;
                    const size_t base =
                        ((size_t)((r >> 10) * 8 + (col >> 6)) * 64) * 1024
                        + (size_t)(r & 1023);
                    g_vth[base + (size_t)(col & 63) * 1024] =
                        __float2half_rn(acc[mt][nt][2 * q] + b0);
                    g_vth[base + (size_t)((col & 63) + 1) * 1024] =
                        __float2half_rn(acc[mt][nt][2 * q + 1] + b1);
                }
            }
        }
    }
}

/* fused QKV projection: grid (24, 16) */
__global__ __launch_bounds__(128, 2) void qkv_gemm(
    const float* __restrict__ bq, const float* __restrict__ bk,
    const float* __restrict__ bv)
{
    const int n0 = blockIdx.x * 128, m0 = blockIdx.y * 128;
    if (n0 < 2048)
        gemm_core<0>(g_xh, g_wh, bq, g_q, ((__half*)0), HIDDEN, HIDDEN, m0, n0, n0);
    else if (n0 < 2560)
        gemm_core<1>(g_xh, g_wh, bk, (float*)0, g_kh, KVW, HIDDEN, m0, n0, n0 - 2048);
    else
        gemm_core<2>(g_xh, g_wh, bv, (float*)0, ((__half*)0), KVW, HIDDEN, m0, n0, n0 - 2560);
}

/* O projection: grid (16, 16) */
__global__ __launch_bounds__(128, 2) void oproj_gemm(
    const float* __restrict__ bo, float* __restrict__ out)
{
    gemm_core<0>(g_attnh, g_woh, bo, out, ((__half*)0), HIDDEN, HIDDEN,
                 blockIdx.y * 128, blockIdx.x * 128, blockIdx.x * 128);
}

/* =================================================================
 * Flash attention fp16 (causal, GQA): 128 q-rows/CTA, 256 thr.
 * K/V fp16 staged via cp.async (V pre-transposed); P stays in
 * registers — for m16n8k16 the S C-frag IS the PV A-frag layout
 * (local half2 packs, zero shuffles). 1 barrier per KV tile.
 * ================================================================= */
#define KSTG  8192                     /* 64 rows x 128 B */
#define ASTG  (2 * KSTG)
#define ATT_SMEM (3 * ASTG)            /* 49152 */

__global__ __launch_bounds__(256, 2) void attn_tc(
    const float* __restrict__ Q, __half* __restrict__ Out)
{
    extern __shared__ char smA[];
    const uint32_t sb = smem_u32(smA);

    const int qt = (int)gridDim.x - 1 - (int)blockIdx.x;  /* longest first */
    const int h = blockIdx.y, b = blockIdx.z, g = h >> 2;
    const int tid = threadIdx.x, lane = tid & 31, w = tid >> 5;
    const int r0 = lane >> 2, a4 = lane & 3;
    const int grp = lane >> 3;

    /* cp.async: thread handles row srow, chunks csel and csel+4 */
    const int srow = tid >> 2, csel = tid & 3;
    const __half* ksrc = g_kh  + ((size_t)(b * SEQ) + srow) * KVW + g * HDIM + csel * 8;
    const __half* vsrc = g_vth + ((size_t)((b * NGROUP + g) * HDIM + srow)) * SEQ + csel * 8;
    uint32_t dOff[2];
#pragma unroll
    for (int i = 0; i < 2; i++)
        dOff[i] = (uint32_t)srow * 128 + ((uint32_t)((csel + 4 * i) ^ (srow & 7)) << 4);

    /* ldsm B-fragment lane constants (128B rows) */
    const uint32_t rown  = (uint32_t)((lane & 7) + ((grp >> 1) << 3));
    const uint32_t rterm = rown * 128;
    const uint32_t r7    = rown & 7;
    const uint32_t cbit  = (uint32_t)(grp & 1);

    /* ---- hoist Q fragments (fp32 -> scaled fp16 half2) ---- */
    uint32_t qf[4][4];
    {
        const float sc = 0.125f;
        const float* qp = Q + (size_t)(b * SEQ + qt * 128 + w * 16) * HIDDEN + h * HDIM;
#pragma unroll
        for (int kc = 0; kc < 4; kc++) {
            const int k = kc * 16 + 2 * a4;
            qf[kc][0] = pack_h2(qp[(size_t)r0 * HIDDEN + k] * sc,
                                qp[(size_t)r0 * HIDDEN + k + 1] * sc);
            qf[kc][1] = pack_h2(qp[(size_t)(r0 + 8) * HIDDEN + k] * sc,
                                qp[(size_t)(r0 + 8) * HIDDEN + k + 1] * sc);
            qf[kc][2] = pack_h2(qp[(size_t)r0 * HIDDEN + k + 8] * sc,
                                qp[(size_t)r0 * HIDDEN + k + 9] * sc);
            qf[kc][3] = pack_h2(qp[(size_t)(r0 + 8) * HIDDEN + k + 8] * sc,
                                qp[(size_t)(r0 + 8) * HIDDEN + k + 9] * sc);
        }
    }

    float o[8][4];
#pragma unroll
    for (int nt = 0; nt < 8; nt++) {
        o[nt][0] = 0.f; o[nt][1] = 0.f; o[nt][2] = 0.f; o[nt][3] = 0.f;
    }
    float mi0 = -1e30f, mi1 = -1e30f, l0s = 0.f, l1s = 0.f;

    const int ktEnd = 2 * qt + 1;

    /* prologue: tiles 0, 1 */
#pragma unroll
    for (int t = 0; t < 2; t++) {
        const uint32_t buf = sb + t * ASTG;
        const __half* kp = ksrc + (size_t)t * 64 * KVW;
        const __half* vp = vsrc + t * 64;
        cp16(buf + dOff[0],        kp);
        cp16(buf + dOff[1],        kp + 32);
        cp16(buf + KSTG + dOff[0], vp);
        cp16(buf + KSTG + dOff[1], vp + 32);
        CP_COMMIT();
    }

    int cur = 0;
    for (int kt = 0; kt <= ktEnd; kt++) {
        CP_WAIT1();
        __syncthreads();

        if (kt + 2 <= ktEnd) {
            int nb = cur + 2; if (nb >= 3) nb -= 3;
            const uint32_t buf = sb + nb * ASTG;
            const __half* kp = ksrc + (size_t)(kt + 2) * 64 * KVW;
            const __half* vp = vsrc + (kt + 2) * 64;
            cp16(buf + dOff[0],        kp);
            cp16(buf + dOff[1],        kp + 32);
            cp16(buf + KSTG + dOff[0], vp);
            cp16(buf + KSTG + dOff[1], vp + 32);
        }
        CP_COMMIT();

        const uint32_t kbuf = sb + cur * ASTG;
        const uint32_t vbuf = kbuf + KSTG;

        /* ---- S = Q K^T ---- */
        float s[8][4];
#pragma unroll
        for (int nt = 0; nt < 8; nt++) {
            s[nt][0] = 0.f; s[nt][1] = 0.f; s[nt][2] = 0.f; s[nt][3] = 0.f;
        }
#pragma unroll
        for (int kc = 0; kc < 4; kc++) {
            const uint32_t kk = ((((uint32_t)(kc << 1)) | cbit) ^ r7) << 4;
#pragma unroll
            for (int nt2 = 0; nt2 < 4; nt2++) {
                uint32_t bf[4];
                ldsm_x4(bf, kbuf + nt2 * 2048 + rterm + kk);
                mma_f16(s[2 * nt2],     qf[kc], bf[0], bf[1]);
                mma_f16(s[2 * nt2 + 1], qf[kc], bf[2], bf[3]);
            }
        }

        /* ---- causal mask (diagonal-band tiles) ---- */
        if (kt >= 2 * qt) {
            const int diff  = (kt - 2 * qt) * 64;
            const int row0g = w * 16 + r0, row1g = row0g + 8;
#pragma unroll
            for (int nt = 0; nt < 8; nt++) {
                const int c0 = nt * 8 + 2 * a4 + diff, c1 = c0 + 1;
                if (c0 > row0g) s[nt][0] = -1e30f;
                if (c1 > row0g) s[nt][1] = -1e30f;
                if (c0 > row1g) s[nt][2] = -1e30f;
                if (c1 > row1g) s[nt][3] = -1e30f;
            }
        }

        /* ---- online softmax ---- */
        float mx0 = -1e30f, mx1 = -1e30f;
#pragma unroll
        for (int nt = 0; nt < 8; nt++) {
            mx0 = fmaxf(mx0, fmaxf(s[nt][0], s[nt][1]));
            mx1 = fmaxf(mx1, fmaxf(s[nt][2], s[nt][3]));
        }
        mx0 = fmaxf(mx0, __shfl_xor_sync(0xffffffffu, mx0, 1));
        mx0 = fmaxf(mx0, __shfl_xor_sync(0xffffffffu, mx0, 2));
        mx1 = fmaxf(mx1, __shfl_xor_sync(0xffffffffu, mx1, 1));
        mx1 = fmaxf(mx1, __shfl_xor_sync(0xffffffffu, mx1, 2));
        const float nm0 = fmaxf(mi0, mx0), nm1 = fmaxf(mi1, mx1);
        const float cr0 = __expf(mi0 - nm0), cr1 = __expf(mi1 - nm1);
        float sum0 = 0.f, sum1 = 0.f;
#pragma unroll
        for (int nt = 0; nt < 8; nt++) {
            s[nt][0] = __expf(s[nt][0] - nm0);
            s[nt][1] = __expf(s[nt][1] - nm0);
            s[nt][2] = __expf(s[nt][2] - nm1);
            s[nt][3] = __expf(s[nt][3] - nm1);
            sum0 += s[nt][0] + s[nt][1];
            sum1 += s[nt][2] + s[nt][3];
        }
        sum0 += __shfl_xor_sync(0xffffffffu, sum0, 1);
        sum0 += __shfl_xor_sync(0xffffffffu, sum0, 2);
        sum1 += __shfl_xor_sync(0xffffffffu, sum1, 1);
        sum1 += __shfl_xor_sync(0xffffffffu, sum1, 2);
        l0s = l0s * cr0 + sum0;  l1s = l1s * cr1 + sum1;
        mi0 = nm0;               mi1 = nm1;
#pragma unroll
        for (int nt = 0; nt < 8; nt++) {
            o[nt][0] *= cr0; o[nt][1] *= cr0;
            o[nt][2] *= cr1; o[nt][3] *= cr1;
        }

        /* ---- O += P @ V : C-frag -> A-frag is a LOCAL repack ---- */
#pragma unroll
        for (int kc = 0; kc < 4; kc++) {
            uint32_t pa[4];
            pa[0] = pack_h2(s[2 * kc][0],     s[2 * kc][1]);
            pa[1] = pack_h2(s[2 * kc][2],     s[2 * kc][3]);
            pa[2] = pack_h2(s[2 * kc + 1][0], s[2 * kc + 1][1]);
            pa[3] = pack_h2(s[2 * kc + 1][2], s[2 * kc + 1][3]);
            const uint32_t kk = ((((uint32_t)(kc << 1)) | cbit) ^ r7) << 4;
#pragma unroll
            for (int nt2 = 0; nt2 < 4; nt2++) {
                uint32_t bf[4];
                ldsm_x4(bf, vbuf + nt2 * 2048 + rterm + kk);
                mma_f16(o[2 * nt2],     pa, bf[0], bf[1]);
                mma_f16(o[2 * nt2 + 1], pa, bf[2], bf[3]);
            }
        }

        cur++; if (cur == 3) cur = 0;
    }

    /* ---- finalize: /l, fp16 out for oproj ---- */
    const float inv0 = 1.f / l0s, inv1 = 1.f / l1s;
    const size_t row0 = (size_t)(b * SEQ + qt * 128 + w * 16 + r0);
#pragma unroll
    for (int nt = 0; nt < 8; nt++) {
        const int col = h * HDIM + nt * 8 + 2 * a4;
        *(uint32_t*)&Out[row0 * HIDDEN + col] =
            pack_h2(o[nt][0] * inv0, o[nt][1] * inv0);
        *(uint32_t*)&Out[(row0 + 8) * HIDDEN + col] =
            pack_h2(o[nt][2] * inv1, o[nt][3] * inv1);
    }
}

/* ================================================================= */
extern "C" void kernel_launch(void* const* d_in, const int* in_sizes, int n_in,
                              void* d_out, int out_size)
{
    (void)in_sizes; (void)n_in; (void)out_size;
    const float* x  = (const float*)d_in[0];
    /* d_in[1] = causal mask, handled analytically */
    const float* Wq = (const float*)d_in[2];
    const float* bq = (const float*)d_in[3];
    const float* Wk = (const float*)d_in[4];
    const float* bk = (const float*)d_in[5];
    const float* Wv = (const float*)d_in[6];
    const float* bv = (const float*)d_in[7];
    const float* Wo = (const float*)d_in[8];
    const float* bo = (const float*)d_in[9];
    float* out = (float*)d_out;

    float* q;
    __half* attn;
    cudaGetSymbolAddress((void**)&q,    g_q);
    cudaGetSymbolAddress((void**)&attn, g_attnh);

    cudaFuncSetAttribute(qkv_gemm,   cudaFuncAttributeMaxDynamicSharedMemorySize, GEMM_SMEM);
    cudaFuncSetAttribute(oproj_gemm, cudaFuncAttributeMaxDynamicSharedMemorySize, GEMM_SMEM);
    cudaFuncSetAttribute(attn_tc,    cudaFuncAttributeMaxDynamicSharedMemorySize, ATT_SMEM);

    /* 1. convert inputs to fp16 */
    cvt_all<<<2048, 256>>>((const float4*)x, (const float4*)Wq,
                           (const float4*)Wk, (const float4*)Wv,
                           (const float4*)Wo);

    /* 2. fused Q/K/V projection (Q fp32; K fp16; V fp16-transposed) */
    qkv_gemm<<<dim3(24, 16), 128, GEMM_SMEM>>>(bq, bk, bv);

    /* 3. causal GQA attention (fp16 tensor cores) */
    attn_tc<<<dim3(SEQ / 128, NHEADS, BATCH), 256, ATT_SMEM>>>(q, attn);

    /* 4. output projection */
    oproj_gemm<<<dim3(16, 16), 128, GEMM_SMEM>>>(bo, out);
}

// round 15
// speedup vs baseline: 2.9574x; 1.0195x over previous
#include <cuda_runtime.h>
#include <cuda_fp16.h>
#include <math.h>
#include <stdint.h>

#define HIDDEN 2048
#define SEQ    1024
#define BATCH  2
#define NHEADS 32
#define NGROUP 8
#define HDIM   64
#define MTOT   (BATCH * SEQ)
#define KVW    (NGROUP * HDIM)    /* 512  */
#define QKVW   (HIDDEN + 2 * KVW) /* 3072 */

/* ---------------- scratch (no cudaMalloc allowed) ---------------- */
__device__ __align__(16) __half g_xh  [MTOT * HIDDEN];
__device__ __align__(16) __half g_wh  [QKVW * HIDDEN];   /* Wq|Wk|Wv */
__device__ __align__(16) __half g_woh [HIDDEN * HIDDEN];
__device__ __align__(16) __half g_qh  [MTOT * HIDDEN];   /* fp16, pre-scaled */
__device__ __align__(16) __half g_kh  [MTOT * KVW];
__device__ __align__(16) __half g_vth [BATCH * NGROUP * HDIM * SEQ]; /* [b,g,d,s] */
__device__ __align__(16) __half g_attnh[MTOT * HIDDEN];

/* ---------------- helpers ---------------- */
__device__ __forceinline__ uint32_t pack_h2(float lo, float hi) {
    __half2 h = __floats2half2_rn(lo, hi);
    return *reinterpret_cast<uint32_t*>(&h);
}
__device__ __forceinline__ uint32_t smem_u32(const void* p) {
    uint32_t a;
    asm("{ .reg .u64 t; cvta.to.shared.u64 t, %1; cvt.u32.u64 %0, t; }"
        : "=r"(a) : "l"(p));
    return a;
}
__device__ __forceinline__ void mma_f16(float* c, const uint32_t* a,
                                        uint32_t b0, uint32_t b1) {
    asm volatile(
        "mma.sync.aligned.m16n8k16.row.col.f32.f16.f16.f32 "
        "{%0,%1,%2,%3}, {%4,%5,%6,%7}, {%8,%9}, {%0,%1,%2,%3};"
        : "+f"(c[0]), "+f"(c[1]), "+f"(c[2]), "+f"(c[3])
        : "r"(a[0]), "r"(a[1]), "r"(a[2]), "r"(a[3]), "r"(b0), "r"(b1));
}
__device__ __forceinline__ void ldsm_x4(uint32_t* r, uint32_t addr) {
    asm volatile("ldmatrix.sync.aligned.m8n8.x4.shared.b16 {%0,%1,%2,%3}, [%4];"
        : "=r"(r[0]), "=r"(r[1]), "=r"(r[2]), "=r"(r[3]) : "r"(addr));
}
__device__ __forceinline__ void cp16(uint32_t dst, const void* src) {
    asm volatile("cp.async.cg.shared.global [%0], [%1], 16;"
                 :: "r"(dst), "l"(src));
}
#define CP_COMMIT() asm volatile("cp.async.commit_group;" ::: "memory")
#define CP_WAIT0()  asm volatile("cp.async.wait_group 0;"  ::: "memory")
#define CP_WAIT1()  asm volatile("cp.async.wait_group 1;"  ::: "memory")

/* =================================================================
 * Pre-convert x, Wq|Wk|Wv, Wo to fp16 (grid-stride, float4 -> uint2).
 * ================================================================= */
__global__ void cvt_all(const float4* __restrict__ x,
                        const float4* __restrict__ wq,
                        const float4* __restrict__ wk,
                        const float4* __restrict__ wv,
                        const float4* __restrict__ wo)
{
    const int64_t N0 = 1048576;
    const int64_t N1 = N0 + 1048576;
    const int64_t N2 = N1 + 262144;
    const int64_t N3 = N2 + 262144;
    const int64_t N4 = N3 + 1048576;
    uint2* xh  = (uint2*)g_xh;
    uint2* wh  = (uint2*)g_wh;
    uint2* wo2 = (uint2*)g_woh;
    for (int64_t i = (int64_t)blockIdx.x * blockDim.x + threadIdx.x;
         i < N4; i += (int64_t)gridDim.x * blockDim.x) {
        float4 v; uint2* dst;
        if (i < N0)      { v = x [i];      dst = xh + i; }
        else if (i < N1) { v = wq[i - N0]; dst = wh + (i - N0); }
        else if (i < N2) { v = wk[i - N1]; dst = wh + 1048576 + (i - N1); }
        else if (i < N3) { v = wv[i - N2]; dst = wh + 1310720 + (i - N2); }
        else             { v = wo[i - N3]; dst = wo2 + (i - N3); }
        uint2 u;
        u.x = pack_h2(v.x, v.y);
        u.y = pack_h2(v.z, v.w);
        *dst = u;
    }
}

/* =================================================================
 * FP16 NT GEMM core: CTA 128x128, 128 threads (4 warps 2x2),
 * warp tile 64x64, BK=64 halves (128B rows), double-buffered
 * cp.async, XOR-swizzled. 64KB smem -> 3 CTAs/SM.
 * MODE: 0 fp32+bias | 1 fp16+bias (K) | 2 fp16+bias transposed (Vt)
 *     | 3 fp16, (acc+bias)*0.125 pre-scaled (Q).
 * ================================================================= */
#define BK    64                       /* halves per chunk */
#define TILEB 16384                    /* 128 rows x 128B  */
#define STAGE (2 * TILEB)
#define GEMM_SMEM (2 * STAGE)          /* 65536 */

template<int MODE>
__device__ __forceinline__ void gemm_core(
    const __half* __restrict__ A, const __half* __restrict__ Bm,
    const float* __restrict__ bias, float* __restrict__ C,
    __half* __restrict__ Ch, int ldc, int K, int m0, int n0B, int n0C)
{
    extern __shared__ char smem[];
    const uint32_t sb = smem_u32(smem);
    const int tid = threadIdx.x, lane = tid & 31, wid = tid >> 5;
    const int wm = (wid & 1) * 64, wn = (wid >> 1) * 64;
    const int grp = lane >> 3;

    const uint32_t xm   = (uint32_t)(lane & 7) << 4;
    const uint32_t rowA = (uint32_t)(wm + (lane & 7) + ((grp & 1) << 3)) * 128;
    const uint32_t rowB = (uint32_t)(wn + (lane & 7) + ((grp >> 1) << 3)) * 128;
    const uint32_t cA   = (uint32_t)(grp >> 1) << 4;
    const uint32_t cB   = (uint32_t)(grp & 1) << 4;

    float acc[4][8][4];
#pragma unroll
    for (int mt = 0; mt < 4; mt++)
#pragma unroll
        for (int nt = 0; nt < 8; nt++) {
            acc[mt][nt][0] = 0.f; acc[mt][nt][1] = 0.f;
            acc[mt][nt][2] = 0.f; acc[mt][nt][3] = 0.f;
        }

    const __half* Ag = A  + (size_t)(m0  + tid) * K;
    const __half* Bg = Bm + (size_t)(n0B + tid) * K;
    const uint32_t sRow = (uint32_t)tid * 128;
    const uint32_t sX   = (uint32_t)(tid & 7) << 4;
    const int nIter = K / BK;

    /* prologue: stage 0 */
#pragma unroll
    for (int i = 0; i < 8; i++) {
        const uint32_t d = sRow + (((uint32_t)i << 4) ^ sX);
        cp16(sb + d,         Ag + i * 8);
        cp16(sb + TILEB + d, Bg + i * 8);
    }
    CP_COMMIT();

    for (int it = 0; it < nIter; it++) {
        CP_WAIT0();
        __syncthreads();

        const uint32_t aB = sb + (it & 1) * STAGE;
        const uint32_t bB = aB + TILEB;
        const uint32_t nx = sb + ((it + 1) & 1) * STAGE;
        const bool pf = (it + 1 < nIter);
        const __half* Ap = Ag + (it + 1) * BK;
        const __half* Bp = Bg + (it + 1) * BK;

#pragma unroll
        for (int ks = 0; ks < 4; ks++) {           /* k16 steps */
            if (pf) {
                const uint32_t d0 = sRow + ((((uint32_t)(2 * ks) << 4))     ^ sX);
                const uint32_t d1 = sRow + ((((uint32_t)(2 * ks + 1) << 4)) ^ sX);
                cp16(nx + d0,         Ap + (2 * ks) * 8);
                cp16(nx + d1,         Ap + (2 * ks + 1) * 8);
                cp16(nx + TILEB + d0, Bp + (2 * ks) * 8);
                cp16(nx + TILEB + d1, Bp + (2 * ks + 1) * 8);
            }
            const uint32_t ck = ((uint32_t)ks << 5);
            uint32_t af[4][4];
#pragma unroll
            for (int mt = 0; mt < 4; mt++)
                ldsm_x4(af[mt], aB + rowA + mt * 2048 + ((ck + cA) ^ xm));
            uint32_t bf[2][4];
            ldsm_x4(bf[0], bB + rowB + ((ck + cB) ^ xm));
#pragma unroll
            for (int nt2 = 0; nt2 < 4; nt2++) {
                const int c = nt2 & 1, n = 1 - c;
                if (nt2 < 3)
                    ldsm_x4(bf[n], bB + rowB + (nt2 + 1) * 2048 + ((ck + cB) ^ xm));
#pragma unroll
                for (int mt = 0; mt < 4; mt++) {
                    mma_f16(acc[mt][2 * nt2],     af[mt], bf[c][0], bf[c][1]);
                    mma_f16(acc[mt][2 * nt2 + 1], af[mt], bf[c][2], bf[c][3]);
                }
            }
        }
        CP_COMMIT();
    }

    const int r0 = lane >> 2, a4 = lane & 3;
#pragma unroll
    for (int mt = 0; mt < 4; mt++) {
#pragma unroll
        for (int nt = 0; nt < 8; nt++) {
            const int col = n0C + wn + nt * 8 + 2 * a4;
            const float b0 = bias[col], b1 = bias[col + 1];
            const int rA = m0 + wm + mt * 16 + r0;
            if (MODE == 0) {
                *(float2*)&C[(size_t)rA * ldc + col] =
                    make_float2(acc[mt][nt][0] + b0, acc[mt][nt][1] + b1);
                *(float2*)&C[(size_t)(rA + 8) * ldc + col] =
                    make_float2(acc[mt][nt][2] + b0, acc[mt][nt][3] + b1);
            } else if (MODE == 1) {
                *(uint32_t*)&Ch[(size_t)rA * ldc + col] =
                    pack_h2(acc[mt][nt][0] + b0, acc[mt][nt][1] + b1);
                *(uint32_t*)&Ch[(size_t)(rA + 8) * ldc + col] =
                    pack_h2(acc[mt][nt][2] + b0, acc[mt][nt][3] + b1);
            } else if (MODE == 3) {
                /* Q: pre-scaled by 1/sqrt(d)=0.125 (exact pow2) */
                *(uint32_t*)&Ch[(size_t)rA * ldc + col] =
                    pack_h2((acc[mt][nt][0] + b0) * 0.125f,
                            (acc[mt][nt][1] + b1) * 0.125f);
                *(uint32_t*)&Ch[(size_t)(rA + 8) * ldc + col] =
                    pack_h2((acc[mt][nt][2] + b0) * 0.125f,
                            (acc[mt][nt][3] + b1) * 0.125f);
            } else {
                /* transposed fp16 store into g_vth[b,g,d,s] */
                const int r1 = rA + 8;
#pragma unroll
                for (int q = 0; q < 2; q++) {
                    const int r = q ? r1 : rA;
                    const size_t base =
                        ((size_t)((r >> 10) * 8 + (col >> 6)) * 64) * 1024
                        + (size_t)(r & 1023);
                    g_vth[base + (size_t)(col & 63) * 1024] =
                        __float2half_rn(acc[mt][nt][2 * q] + b0);
                    g_vth[base + (size_t)((col & 63) + 1) * 1024] =
                        __float2half_rn(acc[mt][nt][2 * q + 1] + b1);
                }
            }
        }
    }
}

/* fused QKV projection: grid (24, 16) */
__global__ __launch_bounds__(128, 3) void qkv_gemm(
    const float* __restrict__ bq, const float* __restrict__ bk,
    const float* __restrict__ bv)
{
    const int n0 = blockIdx.x * 128, m0 = blockIdx.y * 128;
    if (n0 < 2048)
        gemm_core<3>(g_xh, g_wh, bq, (float*)0, g_qh, HIDDEN, HIDDEN, m0, n0, n0);
    else if (n0 < 2560)
        gemm_core<1>(g_xh, g_wh, bk, (float*)0, g_kh, KVW, HIDDEN, m0, n0, n0 - 2048);
    else
        gemm_core<2>(g_xh, g_wh, bv, (float*)0, ((__half*)0), KVW, HIDDEN, m0, n0, n0 - 2560);
}

/* O projection: grid (16, 16) */
__global__ __launch_bounds__(128, 3) void oproj_gemm(
    const float* __restrict__ bo, float* __restrict__ out)
{
    gemm_core<0>(g_attnh, g_woh, bo, out, ((__half*)0), HIDDEN, HIDDEN,
                 blockIdx.y * 128, blockIdx.x * 128, blockIdx.x * 128);
}

/* =================================================================
 * Flash attention fp16 (causal, GQA): 128 q-rows/CTA, 256 thr.
 * Q pre-scaled fp16; K/V fp16 staged via cp.async (V transposed);
 * P stays in registers (C-frag == A-frag layout for m16n8k16).
 * ================================================================= */
#define KSTG  8192                     /* 64 rows x 128 B */
#define ASTG  (2 * KSTG)
#define ATT_SMEM (3 * ASTG)            /* 49152 */

__global__ __launch_bounds__(256, 2) void attn_tc(__half* __restrict__ Out)
{
    extern __shared__ char smA[];
    const uint32_t sb = smem_u32(smA);

    const int qt = (int)gridDim.x - 1 - (int)blockIdx.x;  /* longest first */
    const int h = blockIdx.y, b = blockIdx.z, g = h >> 2;
    const int tid = threadIdx.x, lane = tid & 31, w = tid >> 5;
    const int r0 = lane >> 2, a4 = lane & 3;
    const int grp = lane >> 3;

    const int srow = tid >> 2, csel = tid & 3;
    const __half* ksrc = g_kh  + ((size_t)(b * SEQ) + srow) * KVW + g * HDIM + csel * 8;
    const __half* vsrc = g_vth + ((size_t)((b * NGROUP + g) * HDIM + srow)) * SEQ + csel * 8;
    uint32_t dOff[2];
#pragma unroll
    for (int i = 0; i < 2; i++)
        dOff[i] = (uint32_t)srow * 128 + ((uint32_t)((csel + 4 * i) ^ (srow & 7)) << 4);

    const uint32_t rown  = (uint32_t)((lane & 7) + ((grp >> 1) << 3));
    const uint32_t rterm = rown * 128;
    const uint32_t r7    = rown & 7;
    const uint32_t cbit  = (uint32_t)(grp & 1);

    /* ---- hoist Q fragments: direct 32-bit loads (pre-scaled fp16) ---- */
    uint32_t qf[4][4];
    {
        const __half* qp = g_qh + (size_t)(b * SEQ + qt * 128 + w * 16) * HIDDEN + h * HDIM;
#pragma unroll
        for (int kc = 0; kc < 4; kc++) {
            const int k = kc * 16 + 2 * a4;
            qf[kc][0] = *(const uint32_t*)(qp + (size_t)r0 * HIDDEN + k);
            qf[kc][1] = *(const uint32_t*)(qp + (size_t)(r0 + 8) * HIDDEN + k);
            qf[kc][2] = *(const uint32_t*)(qp + (size_t)r0 * HIDDEN + k + 8);
            qf[kc][3] = *(const uint32_t*)(qp + (size_t)(r0 + 8) * HIDDEN + k + 8);
        }
    }

    float o[8][4];
#pragma unroll
    for (int nt = 0; nt < 8; nt++) {
        o[nt][0] = 0.f; o[nt][1] = 0.f; o[nt][2] = 0.f; o[nt][3] = 0.f;
    }
    float mi0 = -1e30f, mi1 = -1e30f, l0s = 0.f, l1s = 0.f;

    const int ktEnd = 2 * qt + 1;

#pragma unroll
    for (int t = 0; t < 2; t++) {
        const uint32_t buf = sb + t * ASTG;
        const __half* kp = ksrc + (size_t)t * 64 * KVW;
        const __half* vp = vsrc + t * 64;
        cp16(buf + dOff[0],        kp);
        cp16(buf + dOff[1],        kp + 32);
        cp16(buf + KSTG + dOff[0], vp);
        cp16(buf + KSTG + dOff[1], vp + 32);
        CP_COMMIT();
    }

    int cur = 0;
    for (int kt = 0; kt <= ktEnd; kt++) {
        CP_WAIT1();
        __syncthreads();

        if (kt + 2 <= ktEnd) {
            int nb = cur + 2; if (nb >= 3) nb -= 3;
            const uint32_t buf = sb + nb * ASTG;
            const __half* kp = ksrc + (size_t)(kt + 2) * 64 * KVW;
            const __half* vp = vsrc + (kt + 2) * 64;
            cp16(buf + dOff[0],        kp);
            cp16(buf + dOff[1],        kp + 32);
            cp16(buf + KSTG + dOff[0], vp);
            cp16(buf + KSTG + dOff[1], vp + 32);
        }
        CP_COMMIT();

        const uint32_t kbuf = sb + cur * ASTG;
        const uint32_t vbuf = kbuf + KSTG;

        /* ---- S = Q K^T ---- */
        float s[8][4];
#pragma unroll
        for (int nt = 0; nt < 8; nt++) {
            s[nt][0] = 0.f; s[nt][1] = 0.f; s[nt][2] = 0.f; s[nt][3] = 0.f;
        }
#pragma unroll
        for (int kc = 0; kc < 4; kc++) {
            const uint32_t kk = ((((uint32_t)(kc << 1)) | cbit) ^ r7) << 4;
#pragma unroll
            for (int nt2 = 0; nt2 < 4; nt2++) {
                uint32_t bf[4];
                ldsm_x4(bf, kbuf + nt2 * 2048 + rterm + kk);
                mma_f16(s[2 * nt2],     qf[kc], bf[0], bf[1]);
                mma_f16(s[2 * nt2 + 1], qf[kc], bf[2], bf[3]);
            }
        }

        /* ---- causal mask ---- */
        if (kt >= 2 * qt) {
            const int diff  = (kt - 2 * qt) * 64;
            const int row0g = w * 16 + r0, row1g = row0g + 8;
#pragma unroll
            for (int nt = 0; nt < 8; nt++) {
                const int c0 = nt * 8 + 2 * a4 + diff, c1 = c0 + 1;
                if (c0 > row0g) s[nt][0] = -1e30f;
                if (c1 > row0g) s[nt][1] = -1e30f;
                if (c0 > row1g) s[nt][2] = -1e30f;
                if (c1 > row1g) s[nt][3] = -1e30f;
            }
        }

        /* ---- online softmax ---- */
        float mx0 = -1e30f, mx1 = -1e30f;
#pragma unroll
        for (int nt = 0; nt < 8; nt++) {
            mx0 = fmaxf(mx0, fmaxf(s[nt][0], s[nt][1]));
            mx1 = fmaxf(mx1, fmaxf(s[nt][2], s[nt][3]));
        }
        mx0 = fmaxf(mx0, __shfl_xor_sync(0xffffffffu, mx0, 1));
        mx0 = fmaxf(mx0, __shfl_xor_sync(0xffffffffu, mx0, 2));
        mx1 = fmaxf(mx1, __shfl_xor_sync(0xffffffffu, mx1, 1));
        mx1 = fmaxf(mx1, __shfl_xor_sync(0xffffffffu, mx1, 2));
        const float nm0 = fmaxf(mi0, mx0), nm1 = fmaxf(mi1, mx1);
        const float cr0 = __expf(mi0 - nm0), cr1 = __expf(mi1 - nm1);
        float sum0 = 0.f, sum1 = 0.f;
#pragma unroll
        for (int nt = 0; nt < 8; nt++) {
            s[nt][0] = __expf(s[nt][0] - nm0);
            s[nt][1] = __expf(s[nt][1] - nm0);
            s[nt][2] = __expf(s[nt][2] - nm1);
            s[nt][3] = __expf(s[nt][3] - nm1);
            sum0 += s[nt][0] + s[nt][1];
            sum1 += s[nt][2] + s[nt][3];
        }
        sum0 += __shfl_xor_sync(0xffffffffu, sum0, 1);
        sum0 += __shfl_xor_sync(0xffffffffu, sum0, 2);
        sum1 += __shfl_xor_sync(0xffffffffu, sum1, 1);
        sum1 += __shfl_xor_sync(0xffffffffu, sum1, 2);
        l0s = l0s * cr0 + sum0;  l1s = l1s * cr1 + sum1;
        mi0 = nm0;               mi1 = nm1;
#pragma unroll
        for (int nt = 0; nt < 8; nt++) {
            o[nt][0] *= cr0; o[nt][1] *= cr0;
            o[nt][2] *= cr1; o[nt][3] *= cr1;
        }

        /* ---- O += P @ V (local repack) ---- */
#pragma unroll
        for (int kc = 0; kc < 4; kc++) {
            uint32_t pa[4];
            pa[0] = pack_h2(s[2 * kc][0],     s[2 * kc][1]);
            pa[1] = pack_h2(s[2 * kc][2],     s[2 * kc][3]);
            pa[2] = pack_h2(s[2 * kc + 1][0], s[2 * kc + 1][1]);
            pa[3] = pack_h2(s[2 * kc + 1][2], s[2 * kc + 1][3]);
            const uint32_t kk = ((((uint32_t)(kc << 1)) | cbit) ^ r7) << 4;
#pragma unroll
            for (int nt2 = 0; nt2 < 4; nt2++) {
                uint32_t bf[4];
                ldsm_x4(bf, vbuf + nt2 * 2048 + rterm + kk);
                mma_f16(o[2 * nt2],     pa, bf[0], bf[1]);
                mma_f16(o[2 * nt2 + 1], pa, bf[2], bf[3]);
            }
        }

        cur++; if (cur == 3) cur = 0;
    }

    /* ---- finalize ---- */
    const float inv0 = 1.f / l0s, inv1 = 1.f / l1s;
    const size_t row0 = (size_t)(b * SEQ + qt * 128 + w * 16 + r0);
#pragma unroll
    for (int nt = 0; nt < 8; nt++) {
        const int col = h * HDIM + nt * 8 + 2 * a4;
        *(uint32_t*)&Out[row0 * HIDDEN + col] =
            pack_h2(o[nt][0] * inv0, o[nt][1] * inv0);
        *(uint32_t*)&Out[(row0 + 8) * HIDDEN + col] =
            pack_h2(o[nt][2] * inv1, o[nt][3] * inv1);
    }
}

/* ================================================================= */
extern "C" void kernel_launch(void* const* d_in, const int* in_sizes, int n_in,
                              void* d_out, int out_size)
{
    (void)in_sizes; (void)n_in; (void)out_size;
    const float* x  = (const float*)d_in[0];
    /* d_in[1] = causal mask, handled analytically */
    const float* Wq = (const float*)d_in[2];
    const float* bq = (const float*)d_in[3];
    const float* Wk = (const float*)d_in[4];
    const float* bk = (const float*)d_in[5];
    const float* Wv = (const float*)d_in[6];
    const float* bv = (const float*)d_in[7];
    const float* Wo = (const float*)d_in[8];
    const float* bo = (const float*)d_in[9];
    float* out = (float*)d_out;

    __half* attn;
    cudaGetSymbolAddress((void**)&attn, g_attnh);

    cudaFuncSetAttribute(qkv_gemm,   cudaFuncAttributeMaxDynamicSharedMemorySize, GEMM_SMEM);
    cudaFuncSetAttribute(oproj_gemm, cudaFuncAttributeMaxDynamicSharedMemorySize, GEMM_SMEM);
    cudaFuncSetAttribute(attn_tc,    cudaFuncAttributeMaxDynamicSharedMemorySize, ATT_SMEM);

    /* 1. convert inputs to fp16 */
    cvt_all<<<2048, 256>>>((const float4*)x, (const float4*)Wq,
                           (const float4*)Wk, (const float4*)Wv,
                           (const float4*)Wo);

    /* 2. fused Q/K/V projection (Q pre-scaled fp16; K fp16; V fp16-T) */
    qkv_gemm<<<dim3(24, 16), 128, GEMM_SMEM>>>(bq, bk, bv);

    /* 3. causal GQA attention (fp16 tensor cores) */
    attn_tc<<<dim3(SEQ / 128, NHEADS, BATCH), 256, ATT_SMEM>>>(attn);

    /* 4. output projection */
    oproj_gemm<<<dim3(16, 16), 128, GEMM_SMEM>>>(bo, out);
}

// round 16
// speedup vs baseline: 3.3088x; 1.1188x over previous
#include <cuda_runtime.h>
#include <cuda_fp16.h>
#include <math.h>
#include <stdint.h>

#define HIDDEN 2048
#define SEQ    1024
#define BATCH  2
#define NHEADS 32
#define NGROUP 8
#define HDIM   64
#define MTOT   (BATCH * SEQ)
#define KVW    (NGROUP * HDIM)    /* 512  */
#define QKVW   (HIDDEN + 2 * KVW) /* 3072 */

/* ---------------- scratch (no cudaMalloc allowed) ---------------- */
__device__ __align__(16) __half g_xh  [MTOT * HIDDEN];
__device__ __align__(16) __half g_wh  [QKVW * HIDDEN];   /* Wq|Wk|Wv */
__device__ __align__(16) __half g_woh [HIDDEN * HIDDEN];
__device__ __align__(16) __half g_qh  [MTOT * HIDDEN];   /* fp16, pre-scaled */
__device__ __align__(16) __half g_kh  [MTOT * KVW];
__device__ __align__(16) __half g_vth [BATCH * NGROUP * HDIM * SEQ]; /* [b,g,d,s] */
__device__ __align__(16) __half g_attnh[MTOT * HIDDEN];

/* ---------------- helpers ---------------- */
__device__ __forceinline__ uint32_t pack_h2(float lo, float hi) {
    __half2 h = __floats2half2_rn(lo, hi);
    return *reinterpret_cast<uint32_t*>(&h);
}
__device__ __forceinline__ uint32_t smem_u32(const void* p) {
    uint32_t a;
    asm("{ .reg .u64 t; cvta.to.shared.u64 t, %1; cvt.u32.u64 %0, t; }"
        : "=r"(a) : "l"(p));
    return a;
}
__device__ __forceinline__ void mma_f16(float* c, const uint32_t* a,
                                        uint32_t b0, uint32_t b1) {
    asm volatile(
        "mma.sync.aligned.m16n8k16.row.col.f32.f16.f16.f32 "
        "{%0,%1,%2,%3}, {%4,%5,%6,%7}, {%8,%9}, {%0,%1,%2,%3};"
        : "+f"(c[0]), "+f"(c[1]), "+f"(c[2]), "+f"(c[3])
        : "r"(a[0]), "r"(a[1]), "r"(a[2]), "r"(a[3]), "r"(b0), "r"(b1));
}
__device__ __forceinline__ void ldsm_x4(uint32_t* r, uint32_t addr) {
    asm volatile("ldmatrix.sync.aligned.m8n8.x4.shared.b16 {%0,%1,%2,%3}, [%4];"
        : "=r"(r[0]), "=r"(r[1]), "=r"(r[2]), "=r"(r[3]) : "r"(addr));
}
__device__ __forceinline__ void cp16(uint32_t dst, const void* src) {
    asm volatile("cp.async.cg.shared.global [%0], [%1], 16;"
                 :: "r"(dst), "l"(src));
}
#define CP_COMMIT() asm volatile("cp.async.commit_group;" ::: "memory")
#define CP_WAIT0()  asm volatile("cp.async.wait_group 0;"  ::: "memory")
#define CP_WAIT1()  asm volatile("cp.async.wait_group 1;"  ::: "memory")

/* =================================================================
 * Pre-convert x, Wq|Wk|Wv, Wo to fp16 (grid-stride, float4 -> uint2).
 * ================================================================= */
__global__ void cvt_all(const float4* __restrict__ x,
                        const float4* __restrict__ wq,
                        const float4* __restrict__ wk,
                        const float4* __restrict__ wv,
                        const float4* __restrict__ wo)
{
    const int64_t N0 = 1048576;
    const int64_t N1 = N0 + 1048576;
    const int64_t N2 = N1 + 262144;
    const int64_t N3 = N2 + 262144;
    const int64_t N4 = N3 + 1048576;
    uint2* xh  = (uint2*)g_xh;
    uint2* wh  = (uint2*)g_wh;
    uint2* wo2 = (uint2*)g_woh;
    for (int64_t i = (int64_t)blockIdx.x * blockDim.x + threadIdx.x;
         i < N4; i += (int64_t)gridDim.x * blockDim.x) {
        float4 v; uint2* dst;
        if (i < N0)      { v = x [i];      dst = xh + i; }
        else if (i < N1) { v = wq[i - N0]; dst = wh + (i - N0); }
        else if (i < N2) { v = wk[i - N1]; dst = wh + 1048576 + (i - N1); }
        else if (i < N3) { v = wv[i - N2]; dst = wh + 1310720 + (i - N2); }
        else             { v = wo[i - N3]; dst = wo2 + (i - N3); }
        uint2 u;
        u.x = pack_h2(v.x, v.y);
        u.y = pack_h2(v.z, v.w);
        *dst = u;
    }
}

/* =================================================================
 * FP16 NT GEMM core (128 thr): CTA 128x128, 4 warps 2x2, warp 64x64,
 * BK=64 halves, double-buffered cp.async, XOR-swizzled 128B rows.
 * MODE: 1 fp16+bias (K) | 2 fp16+bias transposed (Vt)
 *     | 3 fp16, (acc+bias)*0.125 pre-scaled (Q).
 * ================================================================= */
#define BK    64
#define TILEB 16384
#define STAGE (2 * TILEB)
#define GEMM_SMEM (2 * STAGE)          /* 65536 */

template<int MODE>
__device__ __forceinline__ void gemm_core(
    const __half* __restrict__ A, const __half* __restrict__ Bm,
    const float* __restrict__ bias,
    __half* __restrict__ Ch, int ldc, int K, int m0, int n0B, int n0C)
{
    extern __shared__ char smem[];
    const uint32_t sb = smem_u32(smem);
    const int tid = threadIdx.x, lane = tid & 31, wid = tid >> 5;
    const int wm = (wid & 1) * 64, wn = (wid >> 1) * 64;
    const int grp = lane >> 3;

    const uint32_t xm   = (uint32_t)(lane & 7) << 4;
    const uint32_t rowA = (uint32_t)(wm + (lane & 7) + ((grp & 1) << 3)) * 128;
    const uint32_t rowB = (uint32_t)(wn + (lane & 7) + ((grp >> 1) << 3)) * 128;
    const uint32_t cA   = (uint32_t)(grp >> 1) << 4;
    const uint32_t cB   = (uint32_t)(grp & 1) << 4;

    float acc[4][8][4];
#pragma unroll
    for (int mt = 0; mt < 4; mt++)
#pragma unroll
        for (int nt = 0; nt < 8; nt++) {
            acc[mt][nt][0] = 0.f; acc[mt][nt][1] = 0.f;
            acc[mt][nt][2] = 0.f; acc[mt][nt][3] = 0.f;
        }

    const __half* Ag = A  + (size_t)(m0  + tid) * K;
    const __half* Bg = Bm + (size_t)(n0B + tid) * K;
    const uint32_t sRow = (uint32_t)tid * 128;
    const uint32_t sX   = (uint32_t)(tid & 7) << 4;
    const int nIter = K / BK;

#pragma unroll
    for (int i = 0; i < 8; i++) {
        const uint32_t d = sRow + (((uint32_t)i << 4) ^ sX);
        cp16(sb + d,         Ag + i * 8);
        cp16(sb + TILEB + d, Bg + i * 8);
    }
    CP_COMMIT();

    for (int it = 0; it < nIter; it++) {
        CP_WAIT0();
        __syncthreads();

        const uint32_t aB = sb + (it & 1) * STAGE;
        const uint32_t bB = aB + TILEB;
        const uint32_t nx = sb + ((it + 1) & 1) * STAGE;
        const bool pf = (it + 1 < nIter);
        const __half* Ap = Ag + (it + 1) * BK;
        const __half* Bp = Bg + (it + 1) * BK;

#pragma unroll
        for (int ks = 0; ks < 4; ks++) {
            if (pf) {
                const uint32_t d0 = sRow + ((((uint32_t)(2 * ks) << 4))     ^ sX);
                const uint32_t d1 = sRow + ((((uint32_t)(2 * ks + 1) << 4)) ^ sX);
                cp16(nx + d0,         Ap + (2 * ks) * 8);
                cp16(nx + d1,         Ap + (2 * ks + 1) * 8);
                cp16(nx + TILEB + d0, Bp + (2 * ks) * 8);
                cp16(nx + TILEB + d1, Bp + (2 * ks + 1) * 8);
            }
            const uint32_t ck = ((uint32_t)ks << 5);
            uint32_t af[4][4];
#pragma unroll
            for (int mt = 0; mt < 4; mt++)
                ldsm_x4(af[mt], aB + rowA + mt * 2048 + ((ck + cA) ^ xm));
            uint32_t bf[2][4];
            ldsm_x4(bf[0], bB + rowB + ((ck + cB) ^ xm));
#pragma unroll
            for (int nt2 = 0; nt2 < 4; nt2++) {
                const int c = nt2 & 1, n = 1 - c;
                if (nt2 < 3)
                    ldsm_x4(bf[n], bB + rowB + (nt2 + 1) * 2048 + ((ck + cB) ^ xm));
#pragma unroll
                for (int mt = 0; mt < 4; mt++) {
                    mma_f16(acc[mt][2 * nt2],     af[mt], bf[c][0], bf[c][1]);
                    mma_f16(acc[mt][2 * nt2 + 1], af[mt], bf[c][2], bf[c][3]);
                }
            }
        }
        CP_COMMIT();
    }

    const int r0 = lane >> 2, a4 = lane & 3;
#pragma unroll
    for (int mt = 0; mt < 4; mt++) {
#pragma unroll
        for (int nt = 0; nt < 8; nt++) {
            const int col = n0C + wn + nt * 8 + 2 * a4;
            const float b0 = bias[col], b1 = bias[col + 1];
            const int rA = m0 + wm + mt * 16 + r0;
            if (MODE == 1) {
                *(uint32_t*)&Ch[(size_t)rA * ldc + col] =
                    pack_h2(acc[mt][nt][0] + b0, acc[mt][nt][1] + b1);
                *(uint32_t*)&Ch[(size_t)(rA + 8) * ldc + col] =
                    pack_h2(acc[mt][nt][2] + b0, acc[mt][nt][3] + b1);
            } else if (MODE == 3) {
                *(uint32_t*)&Ch[(size_t)rA * ldc + col] =
                    pack_h2((acc[mt][nt][0] + b0) * 0.125f,
                            (acc[mt][nt][1] + b1) * 0.125f);
                *(uint32_t*)&Ch[(size_t)(rA + 8) * ldc + col] =
                    pack_h2((acc[mt][nt][2] + b0) * 0.125f,
                            (acc[mt][nt][3] + b1) * 0.125f);
            } else {
                const int r1 = rA + 8;
#pragma unroll
                for (int q = 0; q < 2; q++) {
                    const int r = q ? r1 : rA;
                    const size_t base =
                        ((size_t)((r >> 10) * 8 + (col >> 6)) * 64) * 1024
                        + (size_t)(r & 1023);
                    g_vth[base + (size_t)(col & 63) * 1024] =
                        __float2half_rn(acc[mt][nt][2 * q] + b0);
                    g_vth[base + (size_t)((col & 63) + 1) * 1024] =
                        __float2half_rn(acc[mt][nt][2 * q + 1] + b1);
                }
            }
        }
    }
}

/* fused QKV projection: grid (24, 16), 128 threads */
__global__ __launch_bounds__(128, 3) void qkv_gemm(
    const float* __restrict__ bq, const float* __restrict__ bk,
    const float* __restrict__ bv)
{
    const int n0 = blockIdx.x * 128, m0 = blockIdx.y * 128;
    if (n0 < 2048)
        gemm_core<3>(g_xh, g_wh, bq, g_qh, HIDDEN, HIDDEN, m0, n0, n0);
    else if (n0 < 2560)
        gemm_core<1>(g_xh, g_wh, bk, g_kh, KVW, HIDDEN, m0, n0, n0 - 2048);
    else
        gemm_core<2>(g_xh, g_wh, bv, ((__half*)0), KVW, HIDDEN, m0, n0, n0 - 2560);
}

/* =================================================================
 * O projection (256 thr): CTA 128x128, 8 warps 2m x 4n, warp 64x32,
 * BK=64, double-buffered cp.async, XOR-swizzled. Same smem (64KB),
 * 2 CTAs/SM -> ~14 warps/SM at grid 256.
 * ================================================================= */
__global__ __launch_bounds__(256, 2) void oproj_gemm(
    const float* __restrict__ bo, float* __restrict__ out)
{
    extern __shared__ char smem[];
    const uint32_t sb = smem_u32(smem);
    const int m0 = blockIdx.y * 128, n0 = blockIdx.x * 128;
    const int tid = threadIdx.x, lane = tid & 31, wid = tid >> 5;
    const int wm = (wid & 1) * 64, wn = (wid >> 1) * 32;
    const int grp = lane >> 3;

    const uint32_t xm   = (uint32_t)(lane & 7) << 4;
    const uint32_t rowA = (uint32_t)(wm + (lane & 7) + ((grp & 1) << 3)) * 128;
    const uint32_t rowB = (uint32_t)(wn + (lane & 7) + ((grp >> 1) << 3)) * 128;
    const uint32_t cA   = (uint32_t)(grp >> 1) << 4;
    const uint32_t cB   = (uint32_t)(grp & 1) << 4;

    float acc[4][4][4];
#pragma unroll
    for (int mt = 0; mt < 4; mt++)
#pragma unroll
        for (int nt = 0; nt < 4; nt++) {
            acc[mt][nt][0] = 0.f; acc[mt][nt][1] = 0.f;
            acc[mt][nt][2] = 0.f; acc[mt][nt][3] = 0.f;
        }

    /* loaders: thread handles row tid>>1, chunks (tid&1)*4 .. +3 */
    const int arow = tid >> 1, ac4 = (tid & 1) * 4;
    const __half* Ag = g_attnh + (size_t)(m0 + arow) * HIDDEN + ac4 * 8;
    const __half* Bg = g_woh   + (size_t)(n0 + arow) * HIDDEN + ac4 * 8;
    const uint32_t lRow = (uint32_t)arow * 128;
    const uint32_t lX7  = (uint32_t)(arow & 7);
    const int nIter = HIDDEN / BK;

    /* prologue: stage 0 */
#pragma unroll
    for (int i = 0; i < 4; i++) {
        const uint32_t d = lRow + (((uint32_t)(ac4 + i) ^ lX7) << 4);
        cp16(sb + d,         Ag + i * 8);
        cp16(sb + TILEB + d, Bg + i * 8);
    }
    CP_COMMIT();

    for (int it = 0; it < nIter; it++) {
        CP_WAIT0();
        __syncthreads();

        const uint32_t aB = sb + (it & 1) * STAGE;
        const uint32_t bB = aB + TILEB;
        const uint32_t nx = sb + ((it + 1) & 1) * STAGE;
        const bool pf = (it + 1 < nIter);
        const __half* Ap = Ag + (it + 1) * BK;
        const __half* Bp = Bg + (it + 1) * BK;

#pragma unroll
        for (int ks = 0; ks < 4; ks++) {
            if (pf) {
                const uint32_t d = lRow + (((uint32_t)(ac4 + ks) ^ lX7) << 4);
                cp16(nx + d,         Ap + ks * 8);
                cp16(nx + TILEB + d, Bp + ks * 8);
            }
            const uint32_t ck = ((uint32_t)ks << 5);
            uint32_t af[4][4];
#pragma unroll
            for (int mt = 0; mt < 4; mt++)
                ldsm_x4(af[mt], aB + rowA + mt * 2048 + ((ck + cA) ^ xm));
            uint32_t bf[2][4];
#pragma unroll
            for (int ng = 0; ng < 2; ng++)
                ldsm_x4(bf[ng], bB + rowB + ng * 2048 + ((ck + cB) ^ xm));
#pragma unroll
            for (int ng = 0; ng < 2; ng++) {
#pragma unroll
                for (int mt = 0; mt < 4; mt++) {
                    mma_f16(acc[mt][2 * ng],     af[mt], bf[ng][0], bf[ng][1]);
                    mma_f16(acc[mt][2 * ng + 1], af[mt], bf[ng][2], bf[ng][3]);
                }
            }
        }
        CP_COMMIT();
    }

    const int r0 = lane >> 2, a4 = lane & 3;
#pragma unroll
    for (int mt = 0; mt < 4; mt++) {
#pragma unroll
        for (int nt = 0; nt < 4; nt++) {
            const int col = n0 + wn + nt * 8 + 2 * a4;
            const float b0 = bo[col], b1 = bo[col + 1];
            const int rA = m0 + wm + mt * 16 + r0;
            *(float2*)&out[(size_t)rA * HIDDEN + col] =
                make_float2(acc[mt][nt][0] + b0, acc[mt][nt][1] + b1);
            *(float2*)&out[(size_t)(rA + 8) * HIDDEN + col] =
                make_float2(acc[mt][nt][2] + b0, acc[mt][nt][3] + b1);
        }
    }
}

/* =================================================================
 * Flash attention fp16 (causal, GQA): 128 q-rows/CTA, 256 thr.
 * Q pre-scaled fp16; K/V fp16 staged via cp.async (V transposed);
 * P stays in registers (C-frag == A-frag layout for m16n8k16).
 * ================================================================= */
#define KSTG  8192                     /* 64 rows x 128 B */
#define ASTG  (2 * KSTG)
#define ATT_SMEM (3 * ASTG)            /* 49152 */

__global__ __launch_bounds__(256, 2) void attn_tc(__half* __restrict__ Out)
{
    extern __shared__ char smA[];
    const uint32_t sb = smem_u32(smA);

    const int qt = (int)gridDim.x - 1 - (int)blockIdx.x;  /* longest first */
    const int h = blockIdx.y, b = blockIdx.z, g = h >> 2;
    const int tid = threadIdx.x, lane = tid & 31, w = tid >> 5;
    const int r0 = lane >> 2, a4 = lane & 3;
    const int grp = lane >> 3;

    const int srow = tid >> 2, csel = tid & 3;
    const __half* ksrc = g_kh  + ((size_t)(b * SEQ) + srow) * KVW + g * HDIM + csel * 8;
    const __half* vsrc = g_vth + ((size_t)((b * NGROUP + g) * HDIM + srow)) * SEQ + csel * 8;
    uint32_t dOff[2];
#pragma unroll
    for (int i = 0; i < 2; i++)
        dOff[i] = (uint32_t)srow * 128 + ((uint32_t)((csel + 4 * i) ^ (srow & 7)) << 4);

    const uint32_t rown  = (uint32_t)((lane & 7) + ((grp >> 1) << 3));
    const uint32_t rterm = rown * 128;
    const uint32_t r7    = rown & 7;
    const uint32_t cbit  = (uint32_t)(grp & 1);

    uint32_t qf[4][4];
    {
        const __half* qp = g_qh + (size_t)(b * SEQ + qt * 128 + w * 16) * HIDDEN + h * HDIM;
#pragma unroll
        for (int kc = 0; kc < 4; kc++) {
            const int k = kc * 16 + 2 * a4;
            qf[kc][0] = *(const uint32_t*)(qp + (size_t)r0 * HIDDEN + k);
            qf[kc][1] = *(const uint32_t*)(qp + (size_t)(r0 + 8) * HIDDEN + k);
            qf[kc][2] = *(const uint32_t*)(qp + (size_t)r0 * HIDDEN + k + 8);
            qf[kc][3] = *(const uint32_t*)(qp + (size_t)(r0 + 8) * HIDDEN + k + 8);
        }
    }

    float o[8][4];
#pragma unroll
    for (int nt = 0; nt < 8; nt++) {
        o[nt][0] = 0.f; o[nt][1] = 0.f; o[nt][2] = 0.f; o[nt][3] = 0.f;
    }
    float mi0 = -1e30f, mi1 = -1e30f, l0s = 0.f, l1s = 0.f;

    const int ktEnd = 2 * qt + 1;

#pragma unroll
    for (int t = 0; t < 2; t++) {
        const uint32_t buf = sb + t * ASTG;
        const __half* kp = ksrc + (size_t)t * 64 * KVW;
        const __half* vp = vsrc + t * 64;
        cp16(buf + dOff[0],        kp);
        cp16(buf + dOff[1],        kp + 32);
        cp16(buf + KSTG + dOff[0], vp);
        cp16(buf + KSTG + dOff[1], vp + 32);
        CP_COMMIT();
    }

    int cur = 0;
    for (int kt = 0; kt <= ktEnd; kt++) {
        CP_WAIT1();
        __syncthreads();

        if (kt + 2 <= ktEnd) {
            int nb = cur + 2; if (nb >= 3) nb -= 3;
            const uint32_t buf = sb + nb * ASTG;
            const __half* kp = ksrc + (size_t)(kt + 2) * 64 * KVW;
            const __half* vp = vsrc + (kt + 2) * 64;
            cp16(buf + dOff[0],        kp);
            cp16(buf + dOff[1],        kp + 32);
            cp16(buf + KSTG + dOff[0], vp);
            cp16(buf + KSTG + dOff[1], vp + 32);
        }
        CP_COMMIT();

        const uint32_t kbuf = sb + cur * ASTG;
        const uint32_t vbuf = kbuf + KSTG;

        float s[8][4];
#pragma unroll
        for (int nt = 0; nt < 8; nt++) {
            s[nt][0] = 0.f; s[nt][1] = 0.f; s[nt][2] = 0.f; s[nt][3] = 0.f;
        }
#pragma unroll
        for (int kc = 0; kc < 4; kc++) {
            const uint32_t kk = ((((uint32_t)(kc << 1)) | cbit) ^ r7) << 4;
#pragma unroll
            for (int nt2 = 0; nt2 < 4; nt2++) {
                uint32_t bf[4];
                ldsm_x4(bf, kbuf + nt2 * 2048 + rterm + kk);
                mma_f16(s[2 * nt2],     qf[kc], bf[0], bf[1]);
                mma_f16(s[2 * nt2 + 1], qf[kc], bf[2], bf[3]);
            }
        }

        if (kt >= 2 * qt) {
            const int diff  = (kt - 2 * qt) * 64;
            const int row0g = w * 16 + r0, row1g = row0g + 8;
#pragma unroll
            for (int nt = 0; nt < 8; nt++) {
                const int c0 = nt * 8 + 2 * a4 + diff, c1 = c0 + 1;
                if (c0 > row0g) s[nt][0] = -1e30f;
                if (c1 > row0g) s[nt][1] = -1e30f;
                if (c0 > row1g) s[nt][2] = -1e30f;
                if (c1 > row1g) s[nt][3] = -1e30f;
            }
        }

        float mx0 = -1e30f, mx1 = -1e30f;
#pragma unroll
        for (int nt = 0; nt < 8; nt++) {
            mx0 = fmaxf(mx0, fmaxf(s[nt][0], s[nt][1]));
            mx1 = fmaxf(mx1, fmaxf(s[nt][2], s[nt][3]));
        }
        mx0 = fmaxf(mx0, __shfl_xor_sync(0xffffffffu, mx0, 1));
        mx0 = fmaxf(mx0, __shfl_xor_sync(0xffffffffu, mx0, 2));
        mx1 = fmaxf(mx1, __shfl_xor_sync(0xffffffffu, mx1, 1));
        mx1 = fmaxf(mx1, __shfl_xor_sync(0xffffffffu, mx1, 2));
        const float nm0 = fmaxf(mi0, mx0), nm1 = fmaxf(mi1, mx1);
        const float cr0 = __expf(mi0 - nm0), cr1 = __expf(mi1 - nm1);
        float sum0 = 0.f, sum1 = 0.f;
#pragma unroll
        for (int nt = 0; nt < 8; nt++) {
            s[nt][0] = __expf(s[nt][0] - nm0);
            s[nt][1] = __expf(s[nt][1] - nm0);
            s[nt][2] = __expf(s[nt][2] - nm1);
            s[nt][3] = __expf(s[nt][3] - nm1);
            sum0 += s[nt][0] + s[nt][1];
            sum1 += s[nt][2] + s[nt][3];
        }
        sum0 += __shfl_xor_sync(0xffffffffu, sum0, 1);
        sum0 += __shfl_xor_sync(0xffffffffu, sum0, 2);
        sum1 += __shfl_xor_sync(0xffffffffu, sum1, 1);
        sum1 += __shfl_xor_sync(0xffffffffu, sum1, 2);
        l0s = l0s * cr0 + sum0;  l1s = l1s * cr1 + sum1;
        mi0 = nm0;               mi1 = nm1;
#pragma unroll
        for (int nt = 0; nt < 8; nt++) {
            o[nt][0] *= cr0; o[nt][1] *= cr0;
            o[nt][2] *= cr1; o[nt][3] *= cr1;
        }

#pragma unroll
        for (int kc = 0; kc < 4; kc++) {
            uint32_t pa[4];
            pa[0] = pack_h2(s[2 * kc][0],     s[2 * kc][1]);
            pa[1] = pack_h2(s[2 * kc][2],     s[2 * kc][3]);
            pa[2] = pack_h2(s[2 * kc + 1][0], s[2 * kc + 1][1]);
            pa[3] = pack_h2(s[2 * kc + 1][2], s[2 * kc + 1][3]);
            const uint32_t kk = ((((uint32_t)(kc << 1)) | cbit) ^ r7) << 4;
#pragma unroll
            for (int nt2 = 0; nt2 < 4; nt2++) {
                uint32_t bf[4];
                ldsm_x4(bf, vbuf + nt2 * 2048 + rterm + kk);
                mma_f16(o[2 * nt2],     pa, bf[0], bf[1]);
                mma_f16(o[2 * nt2 + 1], pa, bf[2], bf[3]);
            }
        }

        cur++; if (cur == 3) cur = 0;
    }

    const float inv0 = 1.f / l0s, inv1 = 1.f / l1s;
    const size_t row0 = (size_t)(b * SEQ + qt * 128 + w * 16 + r0);
#pragma unroll
    for (int nt = 0; nt < 8; nt++) {
        const int col = h * HDIM + nt * 8 + 2 * a4;
        *(uint32_t*)&Out[row0 * HIDDEN + col] =
            pack_h2(o[nt][0] * inv0, o[nt][1] * inv0);
        *(uint32_t*)&Out[(row0 + 8) * HIDDEN + col] =
            pack_h2(o[nt][2] * inv1, o[nt][3] * inv1);
    }
}

/* ================================================================= */
extern "C" void kernel_launch(void* const* d_in, const int* in_sizes, int n_in,
                              void* d_out, int out_size)
{
    (void)in_sizes; (void)n_in; (void)out_size;
    const float* x  = (const float*)d_in[0];
    /* d_in[1] = causal mask, handled analytically */
    const float* Wq = (const float*)d_in[2];
    const float* bq = (const float*)d_in[3];
    const float* Wk = (const float*)d_in[4];
    const float* bk = (const float*)d_in[5];
    const float* Wv = (const float*)d_in[6];
    const float* bv = (const float*)d_in[7];
    const float* Wo = (const float*)d_in[8];
    const float* bo = (const float*)d_in[9];
    float* out = (float*)d_out;

    __half* attn;
    cudaGetSymbolAddress((void**)&attn, g_attnh);

    cudaFuncSetAttribute(qkv_gemm,   cudaFuncAttributeMaxDynamicSharedMemorySize, GEMM_SMEM);
    cudaFuncSetAttribute(oproj_gemm, cudaFuncAttributeMaxDynamicSharedMemorySize, GEMM_SMEM);
    cudaFuncSetAttribute(attn_tc,    cudaFuncAttributeMaxDynamicSharedMemorySize, ATT_SMEM);

    /* 1. convert inputs to fp16 */
    cvt_all<<<2048, 256>>>((const float4*)x, (const float4*)Wq,
                           (const float4*)Wk, (const float4*)Wv,
                           (const float4*)Wo);

    /* 2. fused Q/K/V projection (Q pre-scaled fp16; K fp16; V fp16-T) */
    qkv_gemm<<<dim3(24, 16), 128, GEMM_SMEM>>>(bq, bk, bv);

    /* 3. causal GQA attention (fp16 tensor cores) */
    attn_tc<<<dim3(SEQ / 128, NHEADS, BATCH), 256, ATT_SMEM>>>(attn);

    /* 4. output projection (256-thread CTAs) */
    oproj_gemm<<<dim3(16, 16), 256, GEMM_SMEM>>>(bo, out);
}

// round 17
// speedup vs baseline: 3.9286x; 1.1873x over previous
#include <cuda_runtime.h>
#include <cuda_fp16.h>
#include <math.h>
#include <stdint.h>

#define HIDDEN 2048
#define SEQ    1024
#define BATCH  2
#define NHEADS 32
#define NGROUP 8
#define HDIM   64
#define MTOT   (BATCH * SEQ)
#define KVW    (NGROUP * HDIM)    /* 512  */
#define QKVW   (HIDDEN + 2 * KVW) /* 3072 */

/* ---------------- scratch (no cudaMalloc allowed) ---------------- */
__device__ __align__(16) __half g_xh  [MTOT * HIDDEN];
__device__ __align__(16) __half g_wh  [QKVW * HIDDEN];   /* Wq|Wk|Wv */
__device__ __align__(16) __half g_woh [HIDDEN * HIDDEN];
__device__ __align__(16) __half g_qh  [MTOT * HIDDEN];   /* fp16, pre-scaled */
__device__ __align__(16) __half g_kh  [MTOT * KVW];
__device__ __align__(16) __half g_vth [BATCH * NGROUP * HDIM * SEQ]; /* [b,g,d,s] */
__device__ __align__(16) __half g_attnh[MTOT * HIDDEN];

/* ---------------- helpers ---------------- */
__device__ __forceinline__ uint32_t pack_h2(float lo, float hi) {
    __half2 h = __floats2half2_rn(lo, hi);
    return *reinterpret_cast<uint32_t*>(&h);
}
__device__ __forceinline__ uint32_t smem_u32(const void* p) {
    uint32_t a;
    asm("{ .reg .u64 t; cvta.to.shared.u64 t, %1; cvt.u32.u64 %0, t; }"
        : "=r"(a) : "l"(p));
    return a;
}
__device__ __forceinline__ void mma_f16(float* c, const uint32_t* a,
                                        uint32_t b0, uint32_t b1) {
    asm volatile(
        "mma.sync.aligned.m16n8k16.row.col.f32.f16.f16.f32 "
        "{%0,%1,%2,%3}, {%4,%5,%6,%7}, {%8,%9}, {%0,%1,%2,%3};"
        : "+f"(c[0]), "+f"(c[1]), "+f"(c[2]), "+f"(c[3])
        : "r"(a[0]), "r"(a[1]), "r"(a[2]), "r"(a[3]), "r"(b0), "r"(b1));
}
__device__ __forceinline__ void ldsm_x4(uint32_t* r, uint32_t addr) {
    asm volatile("ldmatrix.sync.aligned.m8n8.x4.shared.b16 {%0,%1,%2,%3}, [%4];"
        : "=r"(r[0]), "=r"(r[1]), "=r"(r[2]), "=r"(r[3]) : "r"(addr));
}
__device__ __forceinline__ void cp16(uint32_t dst, const void* src) {
    asm volatile("cp.async.cg.shared.global [%0], [%1], 16;"
                 :: "r"(dst), "l"(src));
}
#define CP_COMMIT() asm volatile("cp.async.commit_group;" ::: "memory")
#define CP_WAIT0()  asm volatile("cp.async.wait_group 0;"  ::: "memory")
#define CP_WAIT1()  asm volatile("cp.async.wait_group 1;"  ::: "memory")

/* =================================================================
 * Pre-convert x, Wq|Wk|Wv, Wo to fp16 (grid-stride, float4 -> uint2).
 * ================================================================= */
__global__ void cvt_all(const float4* __restrict__ x,
                        const float4* __restrict__ wq,
                        const float4* __restrict__ wk,
                        const float4* __restrict__ wv,
                        const float4* __restrict__ wo)
{
    const int64_t N0 = 1048576;
    const int64_t N1 = N0 + 1048576;
    const int64_t N2 = N1 + 262144;
    const int64_t N3 = N2 + 262144;
    const int64_t N4 = N3 + 1048576;
    uint2* xh  = (uint2*)g_xh;
    uint2* wh  = (uint2*)g_wh;
    uint2* wo2 = (uint2*)g_woh;
    for (int64_t i = (int64_t)blockIdx.x * blockDim.x + threadIdx.x;
         i < N4; i += (int64_t)gridDim.x * blockDim.x) {
        float4 v; uint2* dst;
        if (i < N0)      { v = x [i];      dst = xh + i; }
        else if (i < N1) { v = wq[i - N0]; dst = wh + (i - N0); }
        else if (i < N2) { v = wk[i - N1]; dst = wh + 1048576 + (i - N1); }
        else if (i < N3) { v = wv[i - N2]; dst = wh + 1310720 + (i - N2); }
        else             { v = wo[i - N3]; dst = wo2 + (i - N3); }
        uint2 u;
        u.x = pack_h2(v.x, v.y);
        u.y = pack_h2(v.z, v.w);
        *dst = u;
    }
}

/* =================================================================
 * FP16 NT GEMM core (256 thr): CTA 128x128, 8 warps 2m x 4n,
 * warp tile 64x32, BK=64 halves, double-buffered cp.async,
 * XOR-swizzled 128B rows. 64KB smem -> 2 CTAs/SM (16 warps).
 * MODE: 0 fp32+bias | 1 fp16+bias (K) | 2 fp16+bias transposed (Vt)
 *     | 3 fp16, (acc+bias)*0.125 pre-scaled (Q).
 * ================================================================= */
#define BK    64
#define TILEB 16384
#define STAGE (2 * TILEB)
#define GEMM_SMEM (2 * STAGE)          /* 65536 */

template<int MODE>
__device__ __forceinline__ void gemm256(
    const __half* __restrict__ A, const __half* __restrict__ Bm,
    const float* __restrict__ bias, float* __restrict__ C,
    __half* __restrict__ Ch, int ldc, int K, int m0, int n0B, int n0C)
{
    extern __shared__ char smem[];
    const uint32_t sb = smem_u32(smem);
    const int tid = threadIdx.x, lane = tid & 31, wid = tid >> 5;
    const int wm = (wid & 1) * 64, wn = (wid >> 1) * 32;
    const int grp = lane >> 3;

    const uint32_t xm   = (uint32_t)(lane & 7) << 4;
    const uint32_t rowA = (uint32_t)(wm + (lane & 7) + ((grp & 1) << 3)) * 128;
    const uint32_t rowB = (uint32_t)(wn + (lane & 7) + ((grp >> 1) << 3)) * 128;
    const uint32_t cA   = (uint32_t)(grp >> 1) << 4;
    const uint32_t cB   = (uint32_t)(grp & 1) << 4;

    float acc[4][4][4];
#pragma unroll
    for (int mt = 0; mt < 4; mt++)
#pragma unroll
        for (int nt = 0; nt < 4; nt++) {
            acc[mt][nt][0] = 0.f; acc[mt][nt][1] = 0.f;
            acc[mt][nt][2] = 0.f; acc[mt][nt][3] = 0.f;
        }

    /* loaders: thread handles row tid>>1, chunk group (tid&1)*4 */
    const int arow = tid >> 1, ac4 = (tid & 1) * 4;
    const __half* Ag = A  + (size_t)(m0  + arow) * K + ac4 * 8;
    const __half* Bg = Bm + (size_t)(n0B + arow) * K + ac4 * 8;
    const uint32_t lRow = (uint32_t)arow * 128;
    const uint32_t lX7  = (uint32_t)(arow & 7);
    const int nIter = K / BK;

    /* prologue: stage 0 */
#pragma unroll
    for (int i = 0; i < 4; i++) {
        const uint32_t d = lRow + (((uint32_t)(ac4 + i) ^ lX7) << 4);
        cp16(sb + d,         Ag + i * 8);
        cp16(sb + TILEB + d, Bg + i * 8);
    }
    CP_COMMIT();

    for (int it = 0; it < nIter; it++) {
        CP_WAIT0();
        __syncthreads();

        const uint32_t aB = sb + (it & 1) * STAGE;
        const uint32_t bB = aB + TILEB;
        const uint32_t nx = sb + ((it + 1) & 1) * STAGE;
        const bool pf = (it + 1 < nIter);
        const __half* Ap = Ag + (it + 1) * BK;
        const __half* Bp = Bg + (it + 1) * BK;

#pragma unroll
        for (int ks = 0; ks < 4; ks++) {
            if (pf) {
                const uint32_t d = lRow + (((uint32_t)(ac4 + ks) ^ lX7) << 4);
                cp16(nx + d,         Ap + ks * 8);
                cp16(nx + TILEB + d, Bp + ks * 8);
            }
            const uint32_t ck = ((uint32_t)ks << 5);
            uint32_t af[4][4];
#pragma unroll
            for (int mt = 0; mt < 4; mt++)
                ldsm_x4(af[mt], aB + rowA + mt * 2048 + ((ck + cA) ^ xm));
            uint32_t bf[2][4];
#pragma unroll
            for (int ng = 0; ng < 2; ng++)
                ldsm_x4(bf[ng], bB + rowB + ng * 2048 + ((ck + cB) ^ xm));
#pragma unroll
            for (int ng = 0; ng < 2; ng++) {
#pragma unroll
                for (int mt = 0; mt < 4; mt++) {
                    mma_f16(acc[mt][2 * ng],     af[mt], bf[ng][0], bf[ng][1]);
                    mma_f16(acc[mt][2 * ng + 1], af[mt], bf[ng][2], bf[ng][3]);
                }
            }
        }
        CP_COMMIT();
    }

    const int r0 = lane >> 2, a4 = lane & 3;
#pragma unroll
    for (int mt = 0; mt < 4; mt++) {
#pragma unroll
        for (int nt = 0; nt < 4; nt++) {
            const int col = n0C + wn + nt * 8 + 2 * a4;
            const float b0 = bias[col], b1 = bias[col + 1];
            const int rA = m0 + wm + mt * 16 + r0;
            if (MODE == 0) {
                *(float2*)&C[(size_t)rA * ldc + col] =
                    make_float2(acc[mt][nt][0] + b0, acc[mt][nt][1] + b1);
                *(float2*)&C[(size_t)(rA + 8) * ldc + col] =
                    make_float2(acc[mt][nt][2] + b0, acc[mt][nt][3] + b1);
            } else if (MODE == 1) {
                *(uint32_t*)&Ch[(size_t)rA * ldc + col] =
                    pack_h2(acc[mt][nt][0] + b0, acc[mt][nt][1] + b1);
                *(uint32_t*)&Ch[(size_t)(rA + 8) * ldc + col] =
                    pack_h2(acc[mt][nt][2] + b0, acc[mt][nt][3] + b1);
            } else if (MODE == 3) {
                *(uint32_t*)&Ch[(size_t)rA * ldc + col] =
                    pack_h2((acc[mt][nt][0] + b0) * 0.125f,
                            (acc[mt][nt][1] + b1) * 0.125f);
                *(uint32_t*)&Ch[(size_t)(rA + 8) * ldc + col] =
                    pack_h2((acc[mt][nt][2] + b0) * 0.125f,
                            (acc[mt][nt][3] + b1) * 0.125f);
            } else {
                /* transposed fp16 store into g_vth[b,g,d,s] */
                const int r1 = rA + 8;
#pragma unroll
                for (int q = 0; q < 2; q++) {
                    const int r = q ? r1 : rA;
                    const size_t base =
                        ((size_t)((r >> 10) * 8 + (col >> 6)) * 64) * 1024
                        + (size_t)(r & 1023);
                    g_vth[base + (size_t)(col & 63) * 1024] =
                        __float2half_rn(acc[mt][nt][2 * q] + b0);
                    g_vth[base + (size_t)((col & 63) + 1) * 1024] =
                        __float2half_rn(acc[mt][nt][2 * q + 1] + b1);
                }
            }
        }
    }
}

/* fused QKV projection: grid (24, 16), 256 threads */
__global__ __launch_bounds__(256, 2) void qkv_gemm(
    const float* __restrict__ bq, const float* __restrict__ bk,
    const float* __restrict__ bv)
{
    const int n0 = blockIdx.x * 128, m0 = blockIdx.y * 128;
    if (n0 < 2048)
        gemm256<3>(g_xh, g_wh, bq, (float*)0, g_qh, HIDDEN, HIDDEN, m0, n0, n0);
    else if (n0 < 2560)
        gemm256<1>(g_xh, g_wh, bk, (float*)0, g_kh, KVW, HIDDEN, m0, n0, n0 - 2048);
    else
        gemm256<2>(g_xh, g_wh, bv, (float*)0, ((__half*)0), KVW, HIDDEN, m0, n0, n0 - 2560);
}

/* O projection: grid (16, 16), 256 threads */
__global__ __launch_bounds__(256, 2) void oproj_gemm(
    const float* __restrict__ bo, float* __restrict__ out)
{
    gemm256<0>(g_attnh, g_woh, bo, out, ((__half*)0), HIDDEN, HIDDEN,
               blockIdx.y * 128, blockIdx.x * 128, blockIdx.x * 128);
}

/* =================================================================
 * Flash attention fp16 (causal, GQA): 128 q-rows/CTA, 256 thr.
 * Q pre-scaled fp16; K/V fp16 staged via cp.async (V transposed);
 * P stays in registers (C-frag == A-frag layout for m16n8k16).
 * ================================================================= */
#define KSTG  8192                     /* 64 rows x 128 B */
#define ASTG  (2 * KSTG)
#define ATT_SMEM (3 * ASTG)            /* 49152 */

__global__ __launch_bounds__(256, 2) void attn_tc(__half* __restrict__ Out)
{
    extern __shared__ char smA[];
    const uint32_t sb = smem_u32(smA);

    const int qt = (int)gridDim.x - 1 - (int)blockIdx.x;  /* longest first */
    const int h = blockIdx.y, b = blockIdx.z, g = h >> 2;
    const int tid = threadIdx.x, lane = tid & 31, w = tid >> 5;
    const int r0 = lane >> 2, a4 = lane & 3;
    const int grp = lane >> 3;

    const int srow = tid >> 2, csel = tid & 3;
    const __half* ksrc = g_kh  + ((size_t)(b * SEQ) + srow) * KVW + g * HDIM + csel * 8;
    const __half* vsrc = g_vth + ((size_t)((b * NGROUP + g) * HDIM + srow)) * SEQ + csel * 8;
    uint32_t dOff[2];
#pragma unroll
    for (int i = 0; i < 2; i++)
        dOff[i] = (uint32_t)srow * 128 + ((uint32_t)((csel + 4 * i) ^ (srow & 7)) << 4);

    const uint32_t rown  = (uint32_t)((lane & 7) + ((grp >> 1) << 3));
    const uint32_t rterm = rown * 128;
    const uint32_t r7    = rown & 7;
    const uint32_t cbit  = (uint32_t)(grp & 1);

    uint32_t qf[4][4];
    {
        const __half* qp = g_qh + (size_t)(b * SEQ + qt * 128 + w * 16) * HIDDEN + h * HDIM;
#pragma unroll
        for (int kc = 0; kc < 4; kc++) {
            const int k = kc * 16 + 2 * a4;
            qf[kc][0] = *(const uint32_t*)(qp + (size_t)r0 * HIDDEN + k);
            qf[kc][1] = *(const uint32_t*)(qp + (size_t)(r0 + 8) * HIDDEN + k);
            qf[kc][2] = *(const uint32_t*)(qp + (size_t)r0 * HIDDEN + k + 8);
            qf[kc][3] = *(const uint32_t*)(qp + (size_t)(r0 + 8) * HIDDEN + k + 8);
        }
    }

    float o[8][4];
#pragma unroll
    for (int nt = 0; nt < 8; nt++) {
        o[nt][0] = 0.f; o[nt][1] = 0.f; o[nt][2] = 0.f; o[nt][3] = 0.f;
    }
    float mi0 = -1e30f, mi1 = -1e30f, l0s = 0.f, l1s = 0.f;

    const int ktEnd = 2 * qt + 1;

#pragma unroll
    for (int t = 0; t < 2; t++) {
        const uint32_t buf = sb + t * ASTG;
        const __half* kp = ksrc + (size_t)t * 64 * KVW;
        const __half* vp = vsrc + t * 64;
        cp16(buf + dOff[0],        kp);
        cp16(buf + dOff[1],        kp + 32);
        cp16(buf + KSTG + dOff[0], vp);
        cp16(buf + KSTG + dOff[1], vp + 32);
        CP_COMMIT();
    }

    int cur = 0;
    for (int kt = 0; kt <= ktEnd; kt++) {
        CP_WAIT1();
        __syncthreads();

        if (kt + 2 <= ktEnd) {
            int nb = cur + 2; if (nb >= 3) nb -= 3;
            const uint32_t buf = sb + nb * ASTG;
            const __half* kp = ksrc + (size_t)(kt + 2) * 64 * KVW;
            const __half* vp = vsrc + (kt + 2) * 64;
            cp16(buf + dOff[0],        kp);
            cp16(buf + dOff[1],        kp + 32);
            cp16(buf + KSTG + dOff[0], vp);
            cp16(buf + KSTG + dOff[1], vp + 32);
        }
        CP_COMMIT();

        const uint32_t kbuf = sb + cur * ASTG;
        const uint32_t vbuf = kbuf + KSTG;

        float s[8][4];
#pragma unroll
        for (int nt = 0; nt < 8; nt++) {
            s[nt][0] = 0.f; s[nt][1] = 0.f; s[nt][2] = 0.f; s[nt][3] = 0.f;
        }
#pragma unroll
        for (int kc = 0; kc < 4; kc++) {
            const uint32_t kk = ((((uint32_t)(kc << 1)) | cbit) ^ r7) << 4;
#pragma unroll
            for (int nt2 = 0; nt2 < 4; nt2++) {
                uint32_t bf[4];
                ldsm_x4(bf, kbuf + nt2 * 2048 + rterm + kk);
                mma_f16(s[2 * nt2],     qf[kc], bf[0], bf[1]);
                mma_f16(s[2 * nt2 + 1], qf[kc], bf[2], bf[3]);
            }
        }

        if (kt >= 2 * qt) {
            const int diff  = (kt - 2 * qt) * 64;
            const int row0g = w * 16 + r0, row1g = row0g + 8;
#pragma unroll
            for (int nt = 0; nt < 8; nt++) {
                const int c0 = nt * 8 + 2 * a4 + diff, c1 = c0 + 1;
                if (c0 > row0g) s[nt][0] = -1e30f;
                if (c1 > row0g) s[nt][1] = -1e30f;
                if (c0 > row1g) s[nt][2] = -1e30f;
                if (c1 > row1g) s[nt][3] = -1e30f;
            }
        }

        float mx0 = -1e30f, mx1 = -1e30f;
#pragma unroll
        for (int nt = 0; nt < 8; nt++) {
            mx0 = fmaxf(mx0, fmaxf(s[nt][0], s[nt][1]));
            mx1 = fmaxf(mx1, fmaxf(s[nt][2], s[nt][3]));
        }
        mx0 = fmaxf(mx0, __shfl_xor_sync(0xffffffffu, mx0, 1));
        mx0 = fmaxf(mx0, __shfl_xor_sync(0xffffffffu, mx0, 2));
        mx1 = fmaxf(mx1, __shfl_xor_sync(0xffffffffu, mx1, 1));
        mx1 = fmaxf(mx1, __shfl_xor_sync(0xffffffffu, mx1, 2));
        const float nm0 = fmaxf(mi0, mx0), nm1 = fmaxf(mi1, mx1);
        const float cr0 = __expf(mi0 - nm0), cr1 = __expf(mi1 - nm1);
        float sum0 = 0.f, sum1 = 0.f;
#pragma unroll
        for (int nt = 0; nt < 8; nt++) {
            s[nt][0] = __expf(s[nt][0] - nm0);
            s[nt][1] = __expf(s[nt][1] - nm0);
            s[nt][2] = __expf(s[nt][2] - nm1);
            s[nt][3] = __expf(s[nt][3] - nm1);
            sum0 += s[nt][0] + s[nt][1];
            sum1 += s[nt][2] + s[nt][3];
        }
        sum0 += __shfl_xor_sync(0xffffffffu, sum0, 1);
        sum0 += __shfl_xor_sync(0xffffffffu, sum0, 2);
        sum1 += __shfl_xor_sync(0xffffffffu, sum1, 1);
        sum1 += __shfl_xor_sync(0xffffffffu, sum1, 2);
        l0s = l0s * cr0 + sum0;  l1s = l1s * cr1 + sum1;
        mi0 = nm0;               mi1 = nm1;
#pragma unroll
        for (int nt = 0; nt < 8; nt++) {
            o[nt][0] *= cr0; o[nt][1] *= cr0;
            o[nt][2] *= cr1; o[nt][3] *= cr1;
        }

#pragma unroll
        for (int kc = 0; kc < 4; kc++) {
            uint32_t pa[4];
            pa[0] = pack_h2(s[2 * kc][0],     s[2 * kc][1]);
            pa[1] = pack_h2(s[2 * kc][2],     s[2 * kc][3]);
            pa[2] = pack_h2(s[2 * kc + 1][0], s[2 * kc + 1][1]);
            pa[3] = pack_h2(s[2 * kc + 1][2], s[2 * kc + 1][3]);
            const uint32_t kk = ((((uint32_t)(kc << 1)) | cbit) ^ r7) << 4;
#pragma unroll
            for (int nt2 = 0; nt2 < 4; nt2++) {
                uint32_t bf[4];
                ldsm_x4(bf, vbuf + nt2 * 2048 + rterm + kk);
                mma_f16(o[2 * nt2],     pa, bf[0], bf[1]);
                mma_f16(o[2 * nt2 + 1], pa, bf[2], bf[3]);
            }
        }

        cur++; if (cur == 3) cur = 0;
    }

    const float inv0 = 1.f / l0s, inv1 = 1.f / l1s;
    const size_t row0 = (size_t)(b * SEQ + qt * 128 + w * 16 + r0);
#pragma unroll
    for (int nt = 0; nt < 8; nt++) {
        const int col = h * HDIM + nt * 8 + 2 * a4;
        *(uint32_t*)&Out[row0 * HIDDEN + col] =
            pack_h2(o[nt][0] * inv0, o[nt][1] * inv0);
        *(uint32_t*)&Out[(row0 + 8) * HIDDEN + col] =
            pack_h2(o[nt][2] * inv1, o[nt][3] * inv1);
    }
}

/* ================================================================= */
extern "C" void kernel_launch(void* const* d_in, const int* in_sizes, int n_in,
                              void* d_out, int out_size)
{
    (void)in_sizes; (void)n_in; (void)out_size;
    const float* x  = (const float*)d_in[0];
    /* d_in[1] = causal mask, handled analytically */
    const float* Wq = (const float*)d_in[2];
    const float* bq = (const float*)d_in[3];
    const float* Wk = (const float*)d_in[4];
    const float* bk = (const float*)d_in[5];
    const float* Wv = (const float*)d_in[6];
    const float* bv = (const float*)d_in[7];
    const float* Wo = (const float*)d_in[8];
    const float* bo = (const float*)d_in[9];
    float* out = (float*)d_out;

    __half* attn;
    cudaGetSymbolAddress((void**)&attn, g_attnh);

    cudaFuncSetAttribute(qkv_gemm,   cudaFuncAttributeMaxDynamicSharedMemorySize, GEMM_SMEM);
    cudaFuncSetAttribute(oproj_gemm, cudaFuncAttributeMaxDynamicSharedMemorySize, GEMM_SMEM);
    cudaFuncSetAttribute(attn_tc,    cudaFuncAttributeMaxDynamicSharedMemorySize, ATT_SMEM);

    /* 1. convert inputs to fp16 */
    cvt_all<<<2048, 256>>>((const float4*)x, (const float4*)Wq,
                           (const float4*)Wk, (const float4*)Wv,
                           (const float4*)Wo);

    /* 2. fused Q/K/V projection (256-thread CTAs) */
    qkv_gemm<<<dim3(24, 16), 256, GEMM_SMEM>>>(bq, bk, bv);

    /* 3. causal GQA attention (fp16 tensor cores) */
    attn_tc<<<dim3(SEQ / 128, NHEADS, BATCH), 256, ATT_SMEM>>>(attn);

    /* 4. output projection (256-thread CTAs) */
    oproj_gemm<<<dim3(16, 16), 256, GEMM_SMEM>>>(bo, out);
}